// round 1
// baseline (speedup 1.0000x reference)
#include <cuda_runtime.h>
#include <math.h>

#define N 4096
#define NHEADS 8
#define NHID 64
#define NFEAT 512
#define NOUT 56

// ---------------- device scratch (static, no allocation) ----------------
__device__ float g_H[(size_t)NHEADS * N * NHID];   // 8 MB: per-head features h = x@W
__device__ float g_s1[NHEADS * N], g_s2[NHEADS * N];
__device__ float g_E1[NHEADS * N], g_E1b[NHEADS * N];
__device__ float g_E2[NHEADS * N], g_E2b[NHEADS * N];
__device__ float g_Z[N * NHID];                    // layer-1 output (head-averaged)
__device__ float g_H2[N * 64];                     // layer-2 features, padded 56->64 (pad = 0)
__device__ float g_s1o[N], g_s2o[N];
__device__ float g_E1o[N], g_E1bo[N], g_E2o[N], g_E2bo[N];
__device__ float g_num2[N * NOUT];
__device__ float g_den2[N];

// ---------------- K0: zero accumulators ----------------
__global__ void k0_zero() {
    int idx = blockIdx.x * blockDim.x + threadIdx.x;
    int stride = gridDim.x * blockDim.x;
    for (int i = idx; i < N * NHID; i += stride) g_Z[i] = 0.f;
    for (int i = idx; i < N * NOUT; i += stride) g_num2[i] = 0.f;
    for (int i = idx; i < N; i += stride) g_den2[i] = 0.f;
}

// ---------------- K1: H[h] = x @ Ws[h]  (M=4096, N=64 per head, K=512) ----------------
// grid (8 heads, 64 row tiles), 256 threads, 64x64 tile, 4x4 micro
__global__ __launch_bounds__(256) void k1_gemm(const float* __restrict__ x,
                                               const float* __restrict__ Ws) {
    __shared__ float As[16][68];   // padded, [k][i]
    __shared__ float Bs[16][64];   // [k][c]
    int bx = blockIdx.x;           // head
    int i0 = blockIdx.y * 64;
    int t = threadIdx.x;
    int tr = t >> 4, tc = t & 15;
    float acc[4][4] = {};
    const float* Bsrc = Ws + (size_t)bx * NFEAT * NHID;

    for (int k0 = 0; k0 < NFEAT; k0 += 16) {
#pragma unroll
        for (int p = 0; p < 4; p++) {
            int i = (t >> 4) + p * 16;
            int k = t & 15;
            As[k][i] = x[(size_t)(i0 + i) * NFEAT + k0 + k];
        }
#pragma unroll
        for (int p = 0; p < 4; p++) {
            int kk = (t >> 6) + p * 4;
            int c = t & 63;
            Bs[kk][c] = Bsrc[(size_t)(k0 + kk) * NHID + c];
        }
        __syncthreads();
#pragma unroll
        for (int k = 0; k < 16; k++) {
            float4 a4 = *(const float4*)&As[k][tr * 4];
            float4 b4 = *(const float4*)&Bs[k][tc * 4];
            float av[4] = {a4.x, a4.y, a4.z, a4.w};
            float bv[4] = {b4.x, b4.y, b4.z, b4.w};
#pragma unroll
            for (int r = 0; r < 4; r++)
#pragma unroll
                for (int c = 0; c < 4; c++) acc[r][c] = fmaf(av[r], bv[c], acc[r][c]);
        }
        __syncthreads();
    }
#pragma unroll
    for (int r = 0; r < 4; r++)
#pragma unroll
        for (int c = 0; c < 4; c++)
            g_H[(size_t)bx * N * NHID + (size_t)(i0 + tr * 4 + r) * NHID + tc * 4 + c] = acc[r][c];
}

// ---------------- K2: s1/s2 + exp tables per (head, node). One warp per (h,i). ----------------
__global__ __launch_bounds__(256) void k2_sv(const float* __restrict__ As_) {
    int wid = (blockIdx.x * 256 + threadIdx.x) >> 5;   // 0..32767
    int lane = threadIdx.x & 31;
    int h = wid >> 12;
    int i = wid & (N - 1);
    const float* hrow = g_H + ((size_t)h * N + i) * NHID;
    const float* a = As_ + h * 2 * NHID;
    float x1 = hrow[lane], x2 = hrow[lane + 32];
    float s1p = x1 * a[lane] + x2 * a[lane + 32];
    float s2p = x1 * a[64 + lane] + x2 * a[96 + lane];
#pragma unroll
    for (int o = 16; o > 0; o >>= 1) {
        s1p += __shfl_xor_sync(0xffffffffu, s1p, o);
        s2p += __shfl_xor_sync(0xffffffffu, s2p, o);
    }
    if (lane == 0) {
        int idx = h * N + i;
        g_s1[idx] = s1p; g_s2[idx] = s2p;
        g_E1[idx] = expf(s1p);        g_E1b[idx] = expf(0.2f * s1p);
        g_E2[idx] = expf(s2p);        g_E2b[idx] = expf(0.2f * s2p);
    }
}

// ---------------- K3: fused layer-1 attention-aggregation ----------------
// grid (64 row-tiles, 2 head-groups), 256 threads.
// Tile: 64 rows x 256 cols (4 heads x 64 feats). Micro 8x8. JC=32 j-chunk.
#define JC 32
#define WS_HSTRIDE 2056   // 32*64 + 8 pad (keeps float4 alignment, breaks head-bank aliasing)
#define K3_SMEM_BYTES ((4 * WS_HSTRIDE + 32 * 256 + 3 * 128 + 256) * 4 + 64 * 33 * 4)

__global__ __launch_bounds__(256) void k3_agg(const int* __restrict__ adj) {
    extern __shared__ float sm[];
    float* WsS  = sm;                               // 4 * 2056 floats (w, [h][j][i])
    float* Hs   = WsS + 4 * WS_HSTRIDE;             // 32 * 256 floats ([j][h*64+f])
    int*   adjS = (int*)(Hs + 32 * 256);            // 64 * 33
    float* s2s  = (float*)(adjS + 64 * 33);         // 4 * 32
    float* E2s  = s2s + 128;
    float* E2bs = E2s + 128;
    float* dens = E2bs + 128;                       // 4 * 64

    int t = threadIdx.x;
    int i0 = blockIdx.x * 64;
    int hBase = blockIdx.y * 4;

    // generation mapping: thread owns (gh, gi) over all j
    int gh = t >> 6, gi = t & 63;
    int sidx = (hBase + gh) * N + i0 + gi;
    float s1v = g_s1[sidx];
    float E1v = g_E1[sidx];
    float E1bv = g_E1b[sidx];
    float den = 0.f;

    // FMA mapping: rowgrp rg (8 rows each), colgrp cg (8 cols each)
    int rg = t >> 5, cg = t & 31;
    int fh = cg >> 3;
    int f0 = (cg & 7) << 3;
    float acc[8][8] = {};

    int warp = t >> 5, lane = t & 31;

    for (int jc = 0; jc < N; jc += JC) {
        // adj tile 64 x 32 (coalesced, padded smem)
#pragma unroll
        for (int rr = 0; rr < 8; rr++) {
            int row = warp * 8 + rr;
            adjS[row * 33 + lane] = adj[(size_t)(i0 + row) * N + jc + lane];
        }
        // per-j scalars for 4 heads
        if (t < 128) {
            int hh = t >> 5, jj = t & 31;
            int gsrc = (hBase + hh) * N + jc + jj;
            s2s[t] = g_s2[gsrc];
            E2bs[t] = g_E2b[gsrc];
        } else {
            int u = t - 128;
            int hh = u >> 5, jj = u & 31;
            E2s[u] = g_E2[(hBase + hh) * N + jc + jj];
        }
        // Hs: 32 j x 256 cols (2048 float4, 8 per thread)
#pragma unroll
        for (int p = 0; p < 8; p++) {
            int idx = p * 256 + t;         // float4 index
            int j = idx >> 6, q = idx & 63;
            int c = q * 4;
            int hh = c >> 6, f = c & 63;
            *(float4*)&Hs[j * 256 + c] =
                *(const float4*)&g_H[((size_t)(hBase + hh) * N + jc + j) * NHID + f];
        }
        __syncthreads();

        // generate attention weights w = adj ? (p ? E1*E2 : E1b*E2b) : 0
#pragma unroll
        for (int j = 0; j < JC; j++) {
            int a = adjS[gi * 33 + j];
            float w = 0.f;
            if (a > 0) {
                float s2v = s2s[gh * 32 + j];
                bool p = (s1v + s2v) >= 0.f;
                w = p ? E1v * E2s[gh * 32 + j] : E1bv * E2bs[gh * 32 + j];
            }
            den += w;
            WsS[gh * WS_HSTRIDE + j * 64 + gi] = w;
        }
        __syncthreads();

        // outer-product accumulate: acc[r][c] += w[i][j] * h[j][f]
#pragma unroll 4
        for (int j = 0; j < JC; j++) {
            float4 w0 = *(const float4*)&WsS[fh * WS_HSTRIDE + j * 64 + rg * 8];
            float4 w1 = *(const float4*)&WsS[fh * WS_HSTRIDE + j * 64 + rg * 8 + 4];
            float4 h0 = *(const float4*)&Hs[j * 256 + cg * 8];
            float4 h1 = *(const float4*)&Hs[j * 256 + cg * 8 + 4];
            float wv[8] = {w0.x, w0.y, w0.z, w0.w, w1.x, w1.y, w1.z, w1.w};
            float hv[8] = {h0.x, h0.y, h0.z, h0.w, h1.x, h1.y, h1.z, h1.w};
#pragma unroll
            for (int r = 0; r < 8; r++)
#pragma unroll
                for (int c = 0; c < 8; c++) acc[r][c] = fmaf(wv[r], hv[c], acc[r][c]);
        }
        __syncthreads();
    }

    dens[gh * 64 + gi] = den;
    __syncthreads();

    // finalize: z += 0.125 * elu(num/den)
#pragma unroll
    for (int r = 0; r < 8; r++) {
        int il = rg * 8 + r;
        float inv = 1.0f / dens[fh * 64 + il];
#pragma unroll
        for (int c = 0; c < 8; c++) {
            float v = acc[r][c] * inv;
            v = (v > 0.f) ? v : expm1f(v);
            atomicAdd(&g_Z[(size_t)(i0 + il) * NHID + f0 + c], 0.125f * v);
        }
    }
}

// ---------------- K4: h2 = z @ W_out (+pad), s1o/s2o, exp tables ----------------
__global__ __launch_bounds__(256) void k4_h2(const float* __restrict__ W_out,
                                             const float* __restrict__ a_out) {
    __shared__ float Wo[64 * 56];
    __shared__ float ao[112];
    __shared__ float zs[64 * 64];
    __shared__ float h2s[64 * 56];
    int t = threadIdx.x;
    int i0 = blockIdx.x * 64;
    for (int idx = t; idx < 64 * 56; idx += 256) Wo[idx] = W_out[idx];
    if (t < 112) ao[t] = a_out[t];
#pragma unroll
    for (int p = 0; p < 4; p++) {
        int idx = p * 256 + t;                 // float4 index (1024 total)
        *(float4*)&zs[idx * 4] =
            *(const float4*)&g_Z[(size_t)(i0 + (idx >> 4)) * 64 + (idx & 15) * 4];
    }
    __syncthreads();
#pragma unroll
    for (int e = 0; e < 14; e++) {
        int idx = e * 256 + t;                 // 3584 = 64*56
        int i = idx / 56, c = idx % 56;
        float s = 0.f;
#pragma unroll
        for (int k = 0; k < 64; k++) s = fmaf(zs[i * 64 + k], Wo[k * 56 + c], s);
        h2s[idx] = s;
        g_H2[(size_t)(i0 + i) * 64 + c] = s;
    }
    for (int idx = t; idx < 64 * 8; idx += 256)
        g_H2[(size_t)(i0 + (idx >> 3)) * 64 + 56 + (idx & 7)] = 0.f;
    __syncthreads();
    if (t < 64) {
        float s1 = 0.f, s2 = 0.f;
#pragma unroll
        for (int c = 0; c < 56; c++) {
            float v = h2s[t * 56 + c];
            s1 = fmaf(v, ao[c], s1);
            s2 = fmaf(v, ao[56 + c], s2);
        }
        int i = i0 + t;
        g_s1o[i] = s1; g_s2o[i] = s2;
        g_E1o[i] = expf(s1);       g_E1bo[i] = expf(0.2f * s1);
        g_E2o[i] = expf(s2);       g_E2bo[i] = expf(0.2f * s2);
    }
}

// ---------------- K5: fused layer-2 aggregation (single "head", 56->64 padded cols) ----------------
// grid (64 row-tiles, 4 j-splits), 128 threads. Tile 64x64, micro 4x8.
__global__ __launch_bounds__(128) void k5_agg2(const int* __restrict__ adj) {
    __shared__ float W2s[32 * 64];
    __shared__ float H2s[32 * 64];
    __shared__ int adjS[64 * 33];
    __shared__ float s2os[32], E2os[32], E2bos[32];
    __shared__ float denS[2 * 64];
    int t = threadIdx.x;
    int i0 = blockIdx.x * 64;
    int j0 = blockIdx.y * 1024;

    int gi = t & 63, half = t >> 6;
    float s1v = g_s1o[i0 + gi];
    float E1v = g_E1o[i0 + gi];
    float E1bv = g_E1bo[i0 + gi];
    float den = 0.f;

    int rg = t >> 3, cg = t & 7;
    float acc[4][8] = {};
    int warp = t >> 5, lane = t & 31;

    for (int jc = j0; jc < j0 + 1024; jc += 32) {
#pragma unroll
        for (int rr = 0; rr < 16; rr++) {
            int row = warp * 16 + rr;
            adjS[row * 33 + lane] = adj[(size_t)(i0 + row) * N + jc + lane];
        }
        if (t < 32) s2os[t] = g_s2o[jc + t];
        else if (t < 64) E2os[t - 32] = g_E2o[jc + t - 32];
        else if (t < 96) E2bos[t - 64] = g_E2bo[jc + t - 64];
#pragma unroll
        for (int p = 0; p < 4; p++) {
            int idx = p * 128 + t;             // float4, 512 total
            int j = idx >> 4, q = idx & 15;
            *(float4*)&H2s[j * 64 + q * 4] =
                *(const float4*)&g_H2[(size_t)(jc + j) * 64 + q * 4];
        }
        __syncthreads();
#pragma unroll
        for (int jj = 0; jj < 16; jj++) {
            int j = half * 16 + jj;
            int a = adjS[gi * 33 + j];
            float w = 0.f;
            if (a > 0) {
                bool p = (s1v + s2os[j]) >= 0.f;
                w = p ? E1v * E2os[j] : E1bv * E2bos[j];
            }
            den += w;
            W2s[j * 64 + gi] = w;
        }
        __syncthreads();
#pragma unroll 4
        for (int j = 0; j < 32; j++) {
            float4 w4 = *(const float4*)&W2s[j * 64 + rg * 4];
            float4 h0 = *(const float4*)&H2s[j * 64 + cg * 8];
            float4 h1 = *(const float4*)&H2s[j * 64 + cg * 8 + 4];
            float wv[4] = {w4.x, w4.y, w4.z, w4.w};
            float hv[8] = {h0.x, h0.y, h0.z, h0.w, h1.x, h1.y, h1.z, h1.w};
#pragma unroll
            for (int r = 0; r < 4; r++)
#pragma unroll
                for (int c = 0; c < 8; c++) acc[r][c] = fmaf(wv[r], hv[c], acc[r][c]);
        }
        __syncthreads();
    }
    denS[half * 64 + gi] = den;
    __syncthreads();
    if (t < 64) atomicAdd(&g_den2[i0 + t], denS[t] + denS[64 + t]);
#pragma unroll
    for (int r = 0; r < 4; r++) {
        int i = i0 + rg * 4 + r;
#pragma unroll
        for (int c = 0; c < 8; c++) {
            int col = cg * 8 + c;
            if (col < NOUT) atomicAdd(&g_num2[(size_t)i * NOUT + col], acc[r][c]);
        }
    }
}

// ---------------- K6: out = softmax(elu(num2/den2)) per row; one warp per row ----------------
__global__ __launch_bounds__(256) void k6_final(float* __restrict__ out) {
    int wid = (blockIdx.x * 256 + threadIdx.x) >> 5;
    int lane = threadIdx.x & 31;
    if (wid >= N) return;
    float invd = 1.0f / g_den2[wid];
    float v1 = g_num2[(size_t)wid * NOUT + lane] * invd;
    v1 = (v1 > 0.f) ? v1 : expm1f(v1);
    float v2 = -1e30f;
    if (lane < 24) {
        v2 = g_num2[(size_t)wid * NOUT + 32 + lane] * invd;
        v2 = (v2 > 0.f) ? v2 : expm1f(v2);
    }
    float m = fmaxf(v1, v2);
#pragma unroll
    for (int o = 16; o > 0; o >>= 1) m = fmaxf(m, __shfl_xor_sync(0xffffffffu, m, o));
    float e1 = expf(v1 - m);
    float e2 = (lane < 24) ? expf(v2 - m) : 0.f;
    float s = e1 + e2;
#pragma unroll
    for (int o = 16; o > 0; o >>= 1) s += __shfl_xor_sync(0xffffffffu, s, o);
    float invs = 1.0f / s;
    out[(size_t)wid * NOUT + lane] = e1 * invs;
    if (lane < 24) out[(size_t)wid * NOUT + 32 + lane] = e2 * invs;
}

// ---------------- launch ----------------
extern "C" void kernel_launch(void* const* d_in, const int* in_sizes, int n_in,
                              void* d_out, int out_size) {
    (void)in_sizes; (void)n_in; (void)out_size;
    const float* x     = (const float*)d_in[0];
    const int*   adj   = (const int*)d_in[1];
    const float* Ws    = (const float*)d_in[2];
    const float* As_   = (const float*)d_in[3];
    const float* W_out = (const float*)d_in[4];
    const float* a_out = (const float*)d_in[5];
    float* out = (float*)d_out;

    cudaFuncSetAttribute(k3_agg, cudaFuncAttributeMaxDynamicSharedMemorySize, K3_SMEM_BYTES);

    k0_zero<<<256, 256>>>();
    k1_gemm<<<dim3(8, 64), 256>>>(x, Ws);
    k2_sv<<<4096, 256>>>(As_);
    k3_agg<<<dim3(64, 2), 256, K3_SMEM_BYTES>>>(adj);
    k4_h2<<<64, 256>>>(W_out, a_out);
    k5_agg2<<<dim3(64, 4), 128>>>(adj);
    k6_final<<<512, 256>>>(out);
}

// round 3
// speedup vs baseline: 4.4525x; 4.4525x over previous
#include <cuda_runtime.h>
#include <cuda_fp16.h>
#include <math.h>
#include <stdint.h>

#define N 4096
#define NHEADS 8
#define NHID 64
#define NFEAT 512
#define NOUT 56

// ---------------- device scratch ----------------
__device__ __half g_xh[(size_t)N * NFEAT];                 // x in fp16
__device__ __half g_Wh[(size_t)NHEADS * NFEAT * NHID];     // Ws in fp16
__device__ __half g_Hf16[(size_t)NHEADS * N * NHID];       // h = x@W, fp16, [h][i][f]
__device__ uint32_t g_adjbits[(size_t)N * 128];            // adjacency bitmask
__device__ float g_s1[NHEADS * N], g_s2[NHEADS * N];
__device__ float g_E1[NHEADS * N], g_E1b[NHEADS * N];
__device__ float g_E2[NHEADS * N], g_E2b[NHEADS * N];
__device__ float g_Z[N * NHID];                            // layer-1 output (head mean)
__device__ __half g_H2f16[(size_t)N * 64];                 // layer-2 features [i][64], cols 56-63 zero
__device__ float g_s1o[N], g_s2o[N];
__device__ float g_E1o[N], g_E1bo[N], g_E2o[N], g_E2bo[N];
__device__ float g_num2[N * NOUT];
__device__ float g_den2[N];

// ---------------- helpers ----------------
__device__ __forceinline__ uint32_t s2u(const void* p) {
    uint32_t a;
    asm("{ .reg .u64 t; cvta.to.shared.u64 t, %1; cvt.u32.u64 %0, t; }" : "=r"(a) : "l"(p));
    return a;
}
#define LDSM_X4(r0, r1, r2, r3, a) \
    asm volatile("ldmatrix.sync.aligned.m8n8.x4.shared.b16 {%0,%1,%2,%3}, [%4];" \
                 : "=r"(r0), "=r"(r1), "=r"(r2), "=r"(r3) : "r"(a))
#define LDSM_X4T(r0, r1, r2, r3, a) \
    asm volatile("ldmatrix.sync.aligned.m8n8.x4.trans.shared.b16 {%0,%1,%2,%3}, [%4];" \
                 : "=r"(r0), "=r"(r1), "=r"(r2), "=r"(r3) : "r"(a))

__device__ __forceinline__ void mma16816(float* c, uint32_t a0, uint32_t a1, uint32_t a2,
                                         uint32_t a3, uint32_t b0, uint32_t b1) {
    asm volatile(
        "mma.sync.aligned.m16n8k16.row.col.f32.f16.f16.f32 "
        "{%0,%1,%2,%3}, {%4,%5,%6,%7}, {%8,%9}, {%0,%1,%2,%3};"
        : "+f"(c[0]), "+f"(c[1]), "+f"(c[2]), "+f"(c[3])
        : "r"(a0), "r"(a1), "r"(a2), "r"(a3), "r"(b0), "r"(b1));
}
__device__ __forceinline__ uint32_t packh2(float lo, float hi) {
    __half2 h = __floats2half2_rn(lo, hi);
    return *(uint32_t*)&h;
}

// ---------------- K0: zero accumulators ----------------
__global__ void k0_zero() {
    int idx = blockIdx.x * blockDim.x + threadIdx.x;
    int stride = gridDim.x * blockDim.x;
    for (int i = idx; i < N * NHID; i += stride) g_Z[i] = 0.f;
    for (int i = idx; i < N * NOUT; i += stride) g_num2[i] = 0.f;
    for (int i = idx; i < N; i += stride) g_den2[i] = 0.f;
}

// ---------------- KX: fp32 -> fp16 conversion of x and Ws ----------------
__global__ void kx_cvt(const float* __restrict__ x, const float* __restrict__ Ws) {
    int idx = blockIdx.x * blockDim.x + threadIdx.x;
    int stride = gridDim.x * blockDim.x;
    for (int i = idx; i < N * NFEAT / 2; i += stride) {
        float2 v = ((const float2*)x)[i];
        ((__half2*)g_xh)[i] = __floats2half2_rn(v.x, v.y);
    }
    for (int i = idx; i < NHEADS * NFEAT * NHID / 2; i += stride) {
        float2 v = ((const float2*)Ws)[i];
        ((__half2*)g_Wh)[i] = __floats2half2_rn(v.x, v.y);
    }
}

// ---------------- KB: adj -> bitmask ----------------
__global__ __launch_bounds__(256) void kb_bits(const int* __restrict__ adj) {
    int w = (blockIdx.x * 256 + threadIdx.x) >> 5;   // 0..16383
    int lane = threadIdx.x & 31;
    int row = w >> 2, quarter = w & 3;
    size_t base = (size_t)row * N + quarter * 1024;
#pragma unroll 4
    for (int it = 0; it < 32; it++) {
        int v = adj[base + it * 32 + lane];
        uint32_t m = __ballot_sync(0xffffffffu, v > 0);
        if (lane == 0) g_adjbits[(size_t)row * 128 + quarter * 32 + it] = m;
    }
}

// ---------------- K1: H[h] = x @ Ws[h] via fp16 mma (M=128/CTA, N=64, K=512) ----------------
#define K1_AS 80
#define K1_BS 144
__global__ __launch_bounds__(256) void k1_mma() {
    __shared__ __align__(16) char Asm[128 * K1_AS];
    __shared__ __align__(16) char Bsm[32 * K1_BS];
    uint32_t Abase = s2u(Asm), Bbase = s2u(Bsm);
    int t = threadIdx.x, w = t >> 5, l = t & 31;
    int i0 = blockIdx.x * 128;
    int h = blockIdx.y;
    int rbase = (w & 3) * 32;
    int ntb = (w >> 2) * 4;            // n-tile base (cols (w>>2)*32)
    float c[2][4][4] = {};
    const __half* wsrc = g_Wh + (size_t)h * NFEAT * NHID;

    for (int kc = 0; kc < NFEAT; kc += 32) {
#pragma unroll
        for (int p = 0; p < 2; p++) {
            int idx = p * 256 + t;
            int row = idx >> 2, q = idx & 3;
            uint4 v = *(const uint4*)(g_xh + (size_t)(i0 + row) * NFEAT + kc + q * 8);
            *(uint4*)(Asm + row * K1_AS + q * 16) = v;
        }
        {
            int row = t >> 3, q = t & 7;
            uint4 v = *(const uint4*)(wsrc + (size_t)(kc + row) * NHID + q * 8);
            *(uint4*)(Bsm + row * K1_BS + q * 16) = v;
        }
        __syncthreads();
        int g = l >> 3;
#pragma unroll
        for (int ks = 0; ks < 2; ks++) {
            uint32_t bq[4][2];
#pragma unroll
            for (int p = 0; p < 2; p++) {
                uint32_t addr = Bbase + (ks * 16 + (g & 1) * 8 + (l & 7)) * K1_BS
                              + (ntb + p * 2 + (g >> 1)) * 16;
                LDSM_X4T(bq[p * 2][0], bq[p * 2][1], bq[p * 2 + 1][0], bq[p * 2 + 1][1], addr);
            }
#pragma unroll
            for (int rf = 0; rf < 2; rf++) {
                uint32_t a0, a1, a2, a3;
                uint32_t addr = Abase + (rbase + rf * 16 + (g & 1) * 8 + (l & 7)) * K1_AS
                              + (ks * 16 + (g >> 1) * 8) * 2;
                LDSM_X4(a0, a1, a2, a3, addr);
#pragma unroll
                for (int nt = 0; nt < 4; nt++)
                    mma16816(c[rf][nt], a0, a1, a2, a3, bq[nt][0], bq[nt][1]);
            }
        }
        __syncthreads();
    }
    __half* dst = g_Hf16 + (size_t)h * N * NHID;
#pragma unroll
    for (int rf = 0; rf < 2; rf++)
#pragma unroll
        for (int nt = 0; nt < 4; nt++) {
            int row0 = i0 + rbase + rf * 16 + (l >> 2);
            int col = (ntb + nt) * 8 + 2 * (l & 3);
            *(uint32_t*)(dst + (size_t)row0 * 64 + col) = packh2(c[rf][nt][0], c[rf][nt][1]);
            *(uint32_t*)(dst + (size_t)(row0 + 8) * 64 + col) = packh2(c[rf][nt][2], c[rf][nt][3]);
        }
}

// ---------------- K2: s1/s2 + exp tables. One warp per (h,i). ----------------
__global__ __launch_bounds__(256) void k2_sv(const float* __restrict__ As_) {
    int wid = (blockIdx.x * 256 + threadIdx.x) >> 5;
    int lane = threadIdx.x & 31;
    int h = wid >> 12;
    int i = wid & (N - 1);
    const __half2* hrow = (const __half2*)(g_Hf16 + ((size_t)h * N + i) * NHID);
    const float* a = As_ + h * 2 * NHID;
    __half2 v = hrow[lane];
    float xl = __low2float(v), xh = __high2float(v);
    float s1p = xl * a[2 * lane] + xh * a[2 * lane + 1];
    float s2p = xl * a[64 + 2 * lane] + xh * a[64 + 2 * lane + 1];
#pragma unroll
    for (int o = 16; o > 0; o >>= 1) {
        s1p += __shfl_xor_sync(0xffffffffu, s1p, o);
        s2p += __shfl_xor_sync(0xffffffffu, s2p, o);
    }
    if (lane == 0) {
        int idx = h * N + i;
        g_s1[idx] = s1p; g_s2[idx] = s2p;
        g_E1[idx] = expf(s1p);   g_E1b[idx] = expf(0.2f * s1p);
        g_E2[idx] = expf(s2p);   g_E2b[idx] = expf(0.2f * s2p);
    }
}

// ---------------- K3: fused layer-1 attention aggregation via fp16 mma ----------------
// grid (32 i-tiles, 4 head-pairs), 256 threads. Warp w: head w>>2, rows (w&3)*32.
// Attention weights generated in registers directly in A-fragment layout.
#define BS_H 4608   // 32 * 144
__global__ __launch_bounds__(256) void k3_mma() {
    __shared__ __align__(16) char Bsm[2 * BS_H];
    __shared__ float scS[192];    // [head][type(s2,E2,E2b)][32]
    __shared__ float dens[256];   // [head][128]
    uint32_t Bbase = s2u(Bsm);
    int t = threadIdx.x, w = t >> 5, l = t & 31;
    int i0 = blockIdx.x * 128, h0 = blockIdx.y * 2;
    int hh = w >> 2;
    int hsel = h0 + hh;
    int rq = (w & 3) * 32 + (l >> 2);
    int jb = 2 * (l & 3);

    float s1r[4], E1r[4], E1br[4];
#pragma unroll
    for (int r = 0; r < 4; r++) {
        int gidx = hsel * N + i0 + rq + r * 8;
        s1r[r] = g_s1[gidx]; E1r[r] = g_E1[gidx]; E1br[r] = g_E1b[gidx];
    }
    float den[4] = {};
    float c[2][8][4] = {};

    for (int jc = 0; jc < N; jc += 32) {
#pragma unroll
        for (int p = 0; p < 2; p++) {
            int idx = p * 256 + t;
            int bh = idx >> 8, rem = idx & 255;
            int j = rem >> 3, q = rem & 7;
            uint4 v = *(const uint4*)(g_Hf16 + ((size_t)(h0 + bh) * N + jc + j) * NHID + q * 8);
            *(uint4*)(Bsm + bh * BS_H + j * 144 + q * 16) = v;
        }
        if (t < 192) {
            int bh = t / 96, rem = t % 96, type = rem >> 5, j = rem & 31;
            const float* src = (type == 0) ? g_s2 : (type == 1 ? g_E2 : g_E2b);
            scS[t] = src[(h0 + bh) * N + jc + j];
        }
        __syncthreads();

        uint32_t aw[4];
#pragma unroll
        for (int r = 0; r < 4; r++)
            aw[r] = g_adjbits[(size_t)(i0 + rq + r * 8) * 128 + (jc >> 5)];

        const float* sc = scS + hh * 96;
        int g = l >> 3;
#pragma unroll
        for (int ks = 0; ks < 2; ks++) {
            float s2v[4], E2v[4], E2bv[4];
#pragma unroll
            for (int q = 0; q < 4; q++) {
                int j = ks * 16 + jb + (q >> 1) * 8 + (q & 1);
                s2v[q] = sc[j]; E2v[q] = sc[32 + j]; E2bv[q] = sc[64 + j];
            }
            float wv[4][4];
#pragma unroll
            for (int r = 0; r < 4; r++)
#pragma unroll
                for (int q = 0; q < 4; q++) {
                    float s12 = s1r[r] + s2v[q];
                    bool pp = s12 >= 0.f;
                    float wt = (pp ? E1r[r] : E1br[r]) * (pp ? E2v[q] : E2bv[q]);
                    int bidx = ks * 16 + jb + (q >> 1) * 8 + (q & 1);
                    wt = ((aw[r] >> bidx) & 1u) ? wt : 0.f;
                    den[r] += wt;
                    wv[r][q] = wt;
                }
            uint32_t bq[8][2];
#pragma unroll
            for (int p = 0; p < 4; p++) {
                uint32_t addr = Bbase + hh * BS_H + (ks * 16 + (g & 1) * 8 + (l & 7)) * 144
                              + (p * 2 + (g >> 1)) * 16;
                LDSM_X4T(bq[p * 2][0], bq[p * 2][1], bq[p * 2 + 1][0], bq[p * 2 + 1][1], addr);
            }
#pragma unroll
            for (int rf = 0; rf < 2; rf++) {
                uint32_t a0 = packh2(wv[rf * 2][0], wv[rf * 2][1]);
                uint32_t a1 = packh2(wv[rf * 2 + 1][0], wv[rf * 2 + 1][1]);
                uint32_t a2 = packh2(wv[rf * 2][2], wv[rf * 2][3]);
                uint32_t a3 = packh2(wv[rf * 2 + 1][2], wv[rf * 2 + 1][3]);
#pragma unroll
                for (int nt = 0; nt < 8; nt++)
                    mma16816(c[rf][nt], a0, a1, a2, a3, bq[nt][0], bq[nt][1]);
            }
        }
        __syncthreads();
    }

#pragma unroll
    for (int r = 0; r < 4; r++) {
        den[r] += __shfl_xor_sync(0xffffffffu, den[r], 1);
        den[r] += __shfl_xor_sync(0xffffffffu, den[r], 2);
    }
    if ((l & 3) == 0) {
#pragma unroll
        for (int r = 0; r < 4; r++)
            dens[hh * 128 + (w & 3) * 32 + (l >> 2) + r * 8] = den[r];
    }
    __syncthreads();

#pragma unroll
    for (int rf = 0; rf < 2; rf++) {
        int r0 = (w & 3) * 32 + rf * 16 + (l >> 2);
        float inv0 = 1.f / dens[hh * 128 + r0];
        float inv1 = 1.f / dens[hh * 128 + r0 + 8];
#pragma unroll
        for (int nt = 0; nt < 8; nt++) {
            int col = nt * 8 + jb;
            float v;
            v = c[rf][nt][0] * inv0; v = (v > 0.f) ? v : expm1f(v);
            atomicAdd(&g_Z[(size_t)(i0 + r0) * 64 + col], 0.125f * v);
            v = c[rf][nt][1] * inv0; v = (v > 0.f) ? v : expm1f(v);
            atomicAdd(&g_Z[(size_t)(i0 + r0) * 64 + col + 1], 0.125f * v);
            v = c[rf][nt][2] * inv1; v = (v > 0.f) ? v : expm1f(v);
            atomicAdd(&g_Z[(size_t)(i0 + r0 + 8) * 64 + col], 0.125f * v);
            v = c[rf][nt][3] * inv1; v = (v > 0.f) ? v : expm1f(v);
            atomicAdd(&g_Z[(size_t)(i0 + r0 + 8) * 64 + col + 1], 0.125f * v);
        }
    }
}

// ---------------- K4: h2 = z @ W_out, s/exp tables, padded fp16 h2 ----------------
__global__ __launch_bounds__(256) void k4_h2(const float* __restrict__ W_out,
                                             const float* __restrict__ a_out) {
    __shared__ float Wo[64 * 56];
    __shared__ float ao[112];
    __shared__ float zs[64 * 64];
    __shared__ float h2s[64 * 56];
    int t = threadIdx.x;
    int i0 = blockIdx.x * 64;
    for (int idx = t; idx < 64 * 56; idx += 256) Wo[idx] = W_out[idx];
    if (t < 112) ao[t] = a_out[t];
#pragma unroll
    for (int p = 0; p < 4; p++) {
        int idx = p * 256 + t;
        *(float4*)&zs[idx * 4] =
            *(const float4*)&g_Z[(size_t)(i0 + (idx >> 4)) * 64 + (idx & 15) * 4];
    }
    __syncthreads();
#pragma unroll
    for (int e = 0; e < 14; e++) {
        int idx = e * 256 + t;
        int i = idx / 56, cc = idx % 56;
        float s = 0.f;
#pragma unroll
        for (int k = 0; k < 64; k++) s = fmaf(zs[i * 64 + k], Wo[k * 56 + cc], s);
        h2s[idx] = s;
        g_H2f16[(size_t)(i0 + i) * 64 + cc] = __float2half(s);
    }
    for (int idx = t; idx < 64 * 8; idx += 256)
        g_H2f16[(size_t)(i0 + (idx >> 3)) * 64 + 56 + (idx & 7)] = __float2half(0.f);
    __syncthreads();
    if (t < 64) {
        float s1 = 0.f, s2 = 0.f;
#pragma unroll
        for (int cc = 0; cc < 56; cc++) {
            float v = h2s[t * 56 + cc];
            s1 = fmaf(v, ao[cc], s1);
            s2 = fmaf(v, ao[56 + cc], s2);
        }
        int i = i0 + t;
        g_s1o[i] = s1; g_s2o[i] = s2;
        g_E1o[i] = expf(s1);    g_E1bo[i] = expf(0.2f * s1);
        g_E2o[i] = expf(s2);    g_E2bo[i] = expf(0.2f * s2);
    }
}

// ---------------- K5: layer-2 aggregation via fp16 mma ----------------
// grid (32 i-tiles, 4 j-splits), 256 threads. Warp w: rows w*16, 64 cols (56+pad).
__global__ __launch_bounds__(256) void k5_mma() {
    __shared__ __align__(16) char Bsm[BS_H];
    __shared__ float scS[96];
    uint32_t Bbase = s2u(Bsm);
    int t = threadIdx.x, w = t >> 5, l = t & 31;
    int i0 = blockIdx.x * 128, jbeg = blockIdx.y * 1024;
    int rq = w * 16 + (l >> 2);
    int jb = 2 * (l & 3);

    float s1r[2], E1r[2], E1br[2];
#pragma unroll
    for (int r = 0; r < 2; r++) {
        int gidx = i0 + rq + r * 8;
        s1r[r] = g_s1o[gidx]; E1r[r] = g_E1o[gidx]; E1br[r] = g_E1bo[gidx];
    }
    float den[2] = {};
    float c[8][4] = {};

    for (int jc = jbeg; jc < jbeg + 1024; jc += 32) {
        {
            int j = t >> 3, q = t & 7;
            uint4 v = *(const uint4*)(g_H2f16 + (size_t)(jc + j) * 64 + q * 8);
            *(uint4*)(Bsm + j * 144 + q * 16) = v;
        }
        if (t < 96) {
            int type = t >> 5, j = t & 31;
            const float* src = (type == 0) ? g_s2o : (type == 1 ? g_E2o : g_E2bo);
            scS[t] = src[jc + j];
        }
        __syncthreads();

        uint32_t aw[2];
#pragma unroll
        for (int r = 0; r < 2; r++)
            aw[r] = g_adjbits[(size_t)(i0 + rq + r * 8) * 128 + (jc >> 5)];

        int g = l >> 3;
#pragma unroll
        for (int ks = 0; ks < 2; ks++) {
            float s2v[4], E2v[4], E2bv[4];
#pragma unroll
            for (int q = 0; q < 4; q++) {
                int j = ks * 16 + jb + (q >> 1) * 8 + (q & 1);
                s2v[q] = scS[j]; E2v[q] = scS[32 + j]; E2bv[q] = scS[64 + j];
            }
            float wv[2][4];
#pragma unroll
            for (int r = 0; r < 2; r++)
#pragma unroll
                for (int q = 0; q < 4; q++) {
                    float s12 = s1r[r] + s2v[q];
                    bool pp = s12 >= 0.f;
                    float wt = (pp ? E1r[r] : E1br[r]) * (pp ? E2v[q] : E2bv[q]);
                    int bidx = ks * 16 + jb + (q >> 1) * 8 + (q & 1);
                    wt = ((aw[r] >> bidx) & 1u) ? wt : 0.f;
                    den[r] += wt;
                    wv[r][q] = wt;
                }
            uint32_t bq[8][2];
#pragma unroll
            for (int p = 0; p < 4; p++) {
                uint32_t addr = Bbase + (ks * 16 + (g & 1) * 8 + (l & 7)) * 144
                              + (p * 2 + (g >> 1)) * 16;
                LDSM_X4T(bq[p * 2][0], bq[p * 2][1], bq[p * 2 + 1][0], bq[p * 2 + 1][1], addr);
            }
            uint32_t a0 = packh2(wv[0][0], wv[0][1]);
            uint32_t a1 = packh2(wv[1][0], wv[1][1]);
            uint32_t a2 = packh2(wv[0][2], wv[0][3]);
            uint32_t a3 = packh2(wv[1][2], wv[1][3]);
#pragma unroll
            for (int nt = 0; nt < 8; nt++)
                mma16816(c[nt], a0, a1, a2, a3, bq[nt][0], bq[nt][1]);
        }
        __syncthreads();
    }

#pragma unroll
    for (int r = 0; r < 2; r++) {
        den[r] += __shfl_xor_sync(0xffffffffu, den[r], 1);
        den[r] += __shfl_xor_sync(0xffffffffu, den[r], 2);
    }
    if ((l & 3) == 0) {
#pragma unroll
        for (int r = 0; r < 2; r++)
            atomicAdd(&g_den2[i0 + rq + r * 8], den[r]);
    }
#pragma unroll
    for (int nt = 0; nt < 7; nt++) {
        int col = nt * 8 + jb;
        int row0 = i0 + rq;
        atomicAdd(&g_num2[(size_t)row0 * NOUT + col], c[nt][0]);
        atomicAdd(&g_num2[(size_t)row0 * NOUT + col + 1], c[nt][1]);
        atomicAdd(&g_num2[(size_t)(row0 + 8) * NOUT + col], c[nt][2]);
        atomicAdd(&g_num2[(size_t)(row0 + 8) * NOUT + col + 1], c[nt][3]);
    }
}

// ---------------- K6: out = softmax(elu(num2/den2)) ----------------
__global__ __launch_bounds__(256) void k6_final(float* __restrict__ out) {
    int wid = (blockIdx.x * 256 + threadIdx.x) >> 5;
    int lane = threadIdx.x & 31;
    if (wid >= N) return;
    float invd = 1.0f / g_den2[wid];
    float v1 = g_num2[(size_t)wid * NOUT + lane] * invd;
    v1 = (v1 > 0.f) ? v1 : expm1f(v1);
    float v2 = -1e30f;
    if (lane < 24) {
        v2 = g_num2[(size_t)wid * NOUT + 32 + lane] * invd;
        v2 = (v2 > 0.f) ? v2 : expm1f(v2);
    }
    float m = fmaxf(v1, v2);
#pragma unroll
    for (int o = 16; o > 0; o >>= 1) m = fmaxf(m, __shfl_xor_sync(0xffffffffu, m, o));
    float e1 = expf(v1 - m);
    float e2 = (lane < 24) ? expf(v2 - m) : 0.f;
    float s = e1 + e2;
#pragma unroll
    for (int o = 16; o > 0; o >>= 1) s += __shfl_xor_sync(0xffffffffu, s, o);
    float invs = 1.0f / s;
    out[(size_t)wid * NOUT + lane] = e1 * invs;
    if (lane < 24) out[(size_t)wid * NOUT + 32 + lane] = e2 * invs;
}

// ---------------- launch ----------------
extern "C" void kernel_launch(void* const* d_in, const int* in_sizes, int n_in,
                              void* d_out, int out_size) {
    (void)in_sizes; (void)n_in; (void)out_size;
    const float* x     = (const float*)d_in[0];
    const int*   adj   = (const int*)d_in[1];
    const float* Ws    = (const float*)d_in[2];
    const float* As_   = (const float*)d_in[3];
    const float* W_out = (const float*)d_in[4];
    const float* a_out = (const float*)d_in[5];
    float* out = (float*)d_out;

    k0_zero<<<256, 256>>>();
    kx_cvt<<<512, 256>>>(x, Ws);
    kb_bits<<<2048, 256>>>(adj);
    k1_mma<<<dim3(32, 8), 256>>>();
    k2_sv<<<4096, 256>>>(As_);
    k3_mma<<<dim3(32, 4), 256>>>();
    k4_h2<<<64, 256>>>(W_out, a_out);
    k5_mma<<<dim3(32, 4), 256>>>();
    k6_final<<<512, 256>>>(out);
}

// round 4
// speedup vs baseline: 5.8707x; 1.3185x over previous
#include <cuda_runtime.h>
#include <cuda_fp16.h>
#include <math.h>
#include <stdint.h>

#define N 4096
#define NHEADS 8
#define NHID 64
#define NFEAT 512
#define NOUT 56

// ---------------- device scratch ----------------
__device__ __half g_xh[(size_t)N * NFEAT];                 // x in fp16
__device__ __half g_Wh[(size_t)NHEADS * NFEAT * NHID];     // Ws in fp16
__device__ __half g_Hf16[(size_t)NHEADS * N * NHID];       // h = x@W, fp16, [h][i][f]
__device__ uint32_t g_adjbits[(size_t)N * 128];            // adjacency bitmask
__device__ float g_s1[NHEADS * N], g_s2[NHEADS * N];
__device__ float g_E1[NHEADS * N], g_E1b[NHEADS * N];
__device__ float g_E2[NHEADS * N], g_E2b[NHEADS * N];
__device__ float g_Z[N * NHID];                            // layer-1 output (head mean)
__device__ __half g_H2f16[(size_t)N * 64];                 // layer-2 features [i][64], cols 56-63 zero
__device__ float g_s1o[N], g_s2o[N];
__device__ float g_E1o[N], g_E1bo[N], g_E2o[N], g_E2bo[N];
__device__ float g_num2[N * NOUT];
__device__ float g_den2[N];

// ---------------- helpers ----------------
__device__ __forceinline__ uint32_t s2u(const void* p) {
    uint32_t a;
    asm("{ .reg .u64 t; cvta.to.shared.u64 t, %1; cvt.u32.u64 %0, t; }" : "=r"(a) : "l"(p));
    return a;
}
#define LDSM_X4(r0, r1, r2, r3, a) \
    asm volatile("ldmatrix.sync.aligned.m8n8.x4.shared.b16 {%0,%1,%2,%3}, [%4];" \
                 : "=r"(r0), "=r"(r1), "=r"(r2), "=r"(r3) : "r"(a))
#define LDSM_X4T(r0, r1, r2, r3, a) \
    asm volatile("ldmatrix.sync.aligned.m8n8.x4.trans.shared.b16 {%0,%1,%2,%3}, [%4];" \
                 : "=r"(r0), "=r"(r1), "=r"(r2), "=r"(r3) : "r"(a))

__device__ __forceinline__ void mma16816(float* c, uint32_t a0, uint32_t a1, uint32_t a2,
                                         uint32_t a3, uint32_t b0, uint32_t b1) {
    asm volatile(
        "mma.sync.aligned.m16n8k16.row.col.f32.f16.f16.f32 "
        "{%0,%1,%2,%3}, {%4,%5,%6,%7}, {%8,%9}, {%0,%1,%2,%3};"
        : "+f"(c[0]), "+f"(c[1]), "+f"(c[2]), "+f"(c[3])
        : "r"(a0), "r"(a1), "r"(a2), "r"(a3), "r"(b0), "r"(b1));
}
__device__ __forceinline__ uint32_t packh2(float lo, float hi) {
    __half2 h = __floats2half2_rn(lo, hi);
    return *(uint32_t*)&h;
}
__device__ __forceinline__ void cpa16(uint32_t dst, const void* src) {
    asm volatile("cp.async.cg.shared.global [%0], [%1], 16;" :: "r"(dst), "l"(src));
}
__device__ __forceinline__ void cpa4(uint32_t dst, const void* src) {
    asm volatile("cp.async.ca.shared.global [%0], [%1], 4;" :: "r"(dst), "l"(src));
}
#define CP_COMMIT() asm volatile("cp.async.commit_group;")
#define CP_WAIT1()  asm volatile("cp.async.wait_group 1;")

// ---------------- KA: merged init (zero + fp16 convert + adj bitmask) ----------------
// grid MUST be 2048 x 256 (bitmask mapping depends on it)
__global__ __launch_bounds__(256) void kA_init(const float* __restrict__ x,
                                               const float* __restrict__ Ws,
                                               const int* __restrict__ adj) {
    int t = threadIdx.x;
    int gid = blockIdx.x * 256 + t;
    int stride = gridDim.x * 256;

    // adj -> bitmask: warp w handles row w>>2, quarter w&3
    int w = gid >> 5, lane = t & 31;
    int row = w >> 2, quarter = w & 3;
    size_t base = (size_t)row * N + quarter * 1024;
#pragma unroll 4
    for (int it = 0; it < 32; it++) {
        int v = adj[base + it * 32 + lane];
        uint32_t m = __ballot_sync(0xffffffffu, v > 0);
        if (lane == 0) g_adjbits[(size_t)row * 128 + quarter * 32 + it] = m;
    }
    // conversions
    for (int i = gid; i < N * NFEAT / 2; i += stride) {
        float2 v = ((const float2*)x)[i];
        ((__half2*)g_xh)[i] = __floats2half2_rn(v.x, v.y);
    }
    for (int i = gid; i < NHEADS * NFEAT * NHID / 2; i += stride) {
        float2 v = ((const float2*)Ws)[i];
        ((__half2*)g_Wh)[i] = __floats2half2_rn(v.x, v.y);
    }
    // zeroing
    for (int i = gid; i < N * NHID; i += stride) g_Z[i] = 0.f;
    for (int i = gid; i < N * NOUT; i += stride) g_num2[i] = 0.f;
    for (int i = gid; i < N; i += stride) g_den2[i] = 0.f;
}

// ---------------- K1: H[h] = x @ Ws[h] via fp16 mma + fused s1/s2/exp epilogue ----------------
#define K1_AS 80
#define K1_BS 144
__global__ __launch_bounds__(256) void k1_mma(const float* __restrict__ As_) {
    __shared__ __align__(16) char Asm[128 * K1_AS];
    __shared__ __align__(16) char Bsm[32 * K1_BS];
    __shared__ __align__(16) __half Hsm[128 * 64];
    uint32_t Abase = s2u(Asm), Bbase = s2u(Bsm);
    int t = threadIdx.x, w = t >> 5, l = t & 31;
    int i0 = blockIdx.x * 128;
    int h = blockIdx.y;
    int rbase = (w & 3) * 32;
    int ntb = (w >> 2) * 4;
    float c[2][4][4] = {};
    const __half* wsrc = g_Wh + (size_t)h * NFEAT * NHID;

    for (int kc = 0; kc < NFEAT; kc += 32) {
#pragma unroll
        for (int p = 0; p < 2; p++) {
            int idx = p * 256 + t;
            int rr = idx >> 2, q = idx & 3;
            uint4 v = *(const uint4*)(g_xh + (size_t)(i0 + rr) * NFEAT + kc + q * 8);
            *(uint4*)(Asm + rr * K1_AS + q * 16) = v;
        }
        {
            int rr = t >> 3, q = t & 7;
            uint4 v = *(const uint4*)(wsrc + (size_t)(kc + rr) * NHID + q * 8);
            *(uint4*)(Bsm + rr * K1_BS + q * 16) = v;
        }
        __syncthreads();
        int g = l >> 3;
#pragma unroll
        for (int ks = 0; ks < 2; ks++) {
            uint32_t bq[4][2];
#pragma unroll
            for (int p = 0; p < 2; p++) {
                uint32_t addr = Bbase + (ks * 16 + (g & 1) * 8 + (l & 7)) * K1_BS
                              + (ntb + p * 2 + (g >> 1)) * 16;
                LDSM_X4T(bq[p * 2][0], bq[p * 2][1], bq[p * 2 + 1][0], bq[p * 2 + 1][1], addr);
            }
#pragma unroll
            for (int rf = 0; rf < 2; rf++) {
                uint32_t a0, a1, a2, a3;
                uint32_t addr = Abase + (rbase + rf * 16 + (g & 1) * 8 + (l & 7)) * K1_AS
                              + (ks * 16 + (g >> 1) * 8) * 2;
                LDSM_X4(a0, a1, a2, a3, addr);
#pragma unroll
                for (int nt = 0; nt < 4; nt++)
                    mma16816(c[rf][nt], a0, a1, a2, a3, bq[nt][0], bq[nt][1]);
            }
        }
        __syncthreads();
    }
    __half* dst = g_Hf16 + (size_t)h * N * NHID;
#pragma unroll
    for (int rf = 0; rf < 2; rf++)
#pragma unroll
        for (int nt = 0; nt < 4; nt++) {
            int rl = rbase + rf * 16 + (l >> 2);
            int col = (ntb + nt) * 8 + 2 * (l & 3);
            uint32_t v01 = packh2(c[rf][nt][0], c[rf][nt][1]);
            uint32_t v23 = packh2(c[rf][nt][2], c[rf][nt][3]);
            *(uint32_t*)(dst + (size_t)(i0 + rl) * 64 + col) = v01;
            *(uint32_t*)(dst + (size_t)(i0 + rl + 8) * 64 + col) = v23;
            *(uint32_t*)(Hsm + rl * 64 + col) = v01;
            *(uint32_t*)(Hsm + (rl + 8) * 64 + col) = v23;
        }
    __syncthreads();

    // fused s1/s2 + exp tables: warp w handles rows w*16..w*16+15
    float a1lo = As_[h * 128 + 2 * l], a1hi = As_[h * 128 + 2 * l + 1];
    float a2lo = As_[h * 128 + 64 + 2 * l], a2hi = As_[h * 128 + 64 + 2 * l + 1];
    for (int rr = 0; rr < 16; rr++) {
        int rl = w * 16 + rr;
        __half2 hv = ((__half2*)(Hsm + rl * 64))[l];
        float xl = __low2float(hv), xh = __high2float(hv);
        float s1p = xl * a1lo + xh * a1hi;
        float s2p = xl * a2lo + xh * a2hi;
#pragma unroll
        for (int o = 16; o > 0; o >>= 1) {
            s1p += __shfl_xor_sync(0xffffffffu, s1p, o);
            s2p += __shfl_xor_sync(0xffffffffu, s2p, o);
        }
        if (l == 0) {
            int idx = h * N + i0 + rl;
            g_s1[idx] = s1p; g_s2[idx] = s2p;
            g_E1[idx] = expf(s1p);  g_E1b[idx] = expf(0.2f * s1p);
            g_E2[idx] = expf(s2p);  g_E2b[idx] = expf(0.2f * s2p);
        }
    }
}

// ---------------- K3: fused layer-1 attention aggregation, double-buffered cp.async ----------------
// grid (64 i-tiles x 4 head-pairs), 256 threads. Warp w: head w>>2, rows (w&3)*16.
// j-chunk = 64, 2-stage pipeline.
__global__ __launch_bounds__(256) void k3_mma() {
    __shared__ __align__(16) char Bsm[2][2][9216];   // [buf][head][64 x 144B]
    __shared__ float scS[2][384];                    // [buf][bh*192 + type*64 + j]
    __shared__ float dens[128];                      // [head][64]
    uint32_t Bb = s2u(Bsm), scb = s2u(scS);
    int t = threadIdx.x, w = t >> 5, l = t & 31;
    int i0 = blockIdx.x * 64, h0 = blockIdx.y * 2;
    int hh = w >> 2;
    int rb = (w & 3) * 16;
    int rq = rb + (l >> 2);           // local row 0..63
    int jb = 2 * (l & 3);
    int g = l >> 3;

    float s1r[2], E1r[2], E1br[2];
#pragma unroll
    for (int r = 0; r < 2; r++) {
        int gidx = (h0 + hh) * N + i0 + rq + r * 8;
        s1r[r] = g_s1[gidx]; E1r[r] = g_E1[gidx]; E1br[r] = g_E1b[gidx];
    }
    float den[2] = {};
    float c[8][4] = {};

    // pipeline loads
    auto issue = [&](int buf, int jc) {
#pragma unroll
        for (int p = 0; p < 4; p++) {
            int idx = p * 256 + t;
            int bh = idx >> 9, rem = idx & 511, j = rem >> 3, q = rem & 7;
            cpa16(Bb + buf * 18432 + bh * 9216 + j * 144 + q * 16,
                  g_Hf16 + ((size_t)(h0 + bh) * N + jc + j) * 64 + q * 8);
        }
        for (int u = t; u < 384; u += 256) {
            int bh = (u >= 192) ? 1 : 0;
            int rem = u - bh * 192;
            int type = rem >> 6, j = rem & 63;
            const float* src = (type == 0) ? g_s2 : (type == 1 ? g_E2 : g_E2b);
            cpa4(scb + buf * 1536 + u * 4, src + (h0 + bh) * N + jc + j);
        }
    };
    issue(0, 0);  CP_COMMIT();
    issue(1, 64); CP_COMMIT();

    for (int s = 0; s < 64; s++) {
        int jc = s * 64, buf = s & 1;
        CP_WAIT1();
        __syncthreads();

        const float* sc = scS[buf] + hh * 192;
        uint32_t awv[2][2];
        {
            uint2 a0 = *(const uint2*)&g_adjbits[(size_t)(i0 + rq) * 128 + (jc >> 5)];
            uint2 a1 = *(const uint2*)&g_adjbits[(size_t)(i0 + rq + 8) * 128 + (jc >> 5)];
            awv[0][0] = a0.x; awv[0][1] = a0.y;
            awv[1][0] = a1.x; awv[1][1] = a1.y;
        }
        uint32_t Bb2 = Bb + buf * 18432 + hh * 9216;
#pragma unroll
        for (int ks = 0; ks < 4; ks++) {
            float wv[2][4];
#pragma unroll
            for (int q = 0; q < 4; q++) {
                int jl = ks * 16 + jb + (q >> 1) * 8 + (q & 1);
                float s2v = sc[jl], E2v = sc[64 + jl], E2bv = sc[128 + jl];
                int word = ks >> 1, bit = jl & 31;
#pragma unroll
                for (int r = 0; r < 2; r++) {
                    bool pp = (s1r[r] + s2v) >= 0.f;
                    float wt = pp ? E1r[r] * E2v : E1br[r] * E2bv;
                    wt = ((awv[r][word] >> bit) & 1u) ? wt : 0.f;
                    den[r] += wt;
                    wv[r][q] = wt;
                }
            }
            uint32_t bq[8][2];
#pragma unroll
            for (int p = 0; p < 4; p++) {
                uint32_t addr = Bb2 + (ks * 16 + (g & 1) * 8 + (l & 7)) * 144
                              + (p * 2 + (g >> 1)) * 16;
                LDSM_X4T(bq[p * 2][0], bq[p * 2][1], bq[p * 2 + 1][0], bq[p * 2 + 1][1], addr);
            }
            uint32_t a0 = packh2(wv[0][0], wv[0][1]);
            uint32_t a1 = packh2(wv[1][0], wv[1][1]);
            uint32_t a2 = packh2(wv[0][2], wv[0][3]);
            uint32_t a3 = packh2(wv[1][2], wv[1][3]);
#pragma unroll
            for (int nt = 0; nt < 8; nt++)
                mma16816(c[nt], a0, a1, a2, a3, bq[nt][0], bq[nt][1]);
        }
        __syncthreads();
        if (s < 62) issue(buf, jc + 128);
        CP_COMMIT();
    }

#pragma unroll
    for (int r = 0; r < 2; r++) {
        den[r] += __shfl_xor_sync(0xffffffffu, den[r], 1);
        den[r] += __shfl_xor_sync(0xffffffffu, den[r], 2);
    }
    if ((l & 3) == 0) {
        dens[hh * 64 + rq] = den[0];
        dens[hh * 64 + rq + 8] = den[1];
    }
    __syncthreads();

    float inv0 = 1.f / dens[hh * 64 + rq];
    float inv1 = 1.f / dens[hh * 64 + rq + 8];
#pragma unroll
    for (int nt = 0; nt < 8; nt++) {
        int col = nt * 8 + jb;
        float v;
        v = c[nt][0] * inv0; v = (v > 0.f) ? v : expm1f(v);
        atomicAdd(&g_Z[(size_t)(i0 + rq) * 64 + col], 0.125f * v);
        v = c[nt][1] * inv0; v = (v > 0.f) ? v : expm1f(v);
        atomicAdd(&g_Z[(size_t)(i0 + rq) * 64 + col + 1], 0.125f * v);
        v = c[nt][2] * inv1; v = (v > 0.f) ? v : expm1f(v);
        atomicAdd(&g_Z[(size_t)(i0 + rq + 8) * 64 + col], 0.125f * v);
        v = c[nt][3] * inv1; v = (v > 0.f) ? v : expm1f(v);
        atomicAdd(&g_Z[(size_t)(i0 + rq + 8) * 64 + col + 1], 0.125f * v);
    }
}

// ---------------- K4: h2 = z @ W_out, s/exp tables, padded fp16 h2 ----------------
__global__ __launch_bounds__(256) void k4_h2(const float* __restrict__ W_out,
                                             const float* __restrict__ a_out) {
    __shared__ float Wo[64 * 56];
    __shared__ float ao[112];
    __shared__ float zs[64 * 64];
    __shared__ float h2s[64 * 56];
    int t = threadIdx.x;
    int i0 = blockIdx.x * 64;
    for (int idx = t; idx < 64 * 56; idx += 256) Wo[idx] = W_out[idx];
    if (t < 112) ao[t] = a_out[t];
#pragma unroll
    for (int p = 0; p < 4; p++) {
        int idx = p * 256 + t;
        *(float4*)&zs[idx * 4] =
            *(const float4*)&g_Z[(size_t)(i0 + (idx >> 4)) * 64 + (idx & 15) * 4];
    }
    __syncthreads();
#pragma unroll
    for (int e = 0; e < 14; e++) {
        int idx = e * 256 + t;
        int i = idx / 56, cc = idx % 56;
        float s = 0.f;
#pragma unroll
        for (int k = 0; k < 64; k++) s = fmaf(zs[i * 64 + k], Wo[k * 56 + cc], s);
        h2s[idx] = s;
        g_H2f16[(size_t)(i0 + i) * 64 + cc] = __float2half(s);
    }
    for (int idx = t; idx < 64 * 8; idx += 256)
        g_H2f16[(size_t)(i0 + (idx >> 3)) * 64 + 56 + (idx & 7)] = __float2half(0.f);
    __syncthreads();
    if (t < 64) {
        float s1 = 0.f, s2 = 0.f;
#pragma unroll
        for (int cc = 0; cc < 56; cc++) {
            float v = h2s[t * 56 + cc];
            s1 = fmaf(v, ao[cc], s1);
            s2 = fmaf(v, ao[56 + cc], s2);
        }
        int i = i0 + t;
        g_s1o[i] = s1; g_s2o[i] = s2;
        g_E1o[i] = expf(s1);    g_E1bo[i] = expf(0.2f * s1);
        g_E2o[i] = expf(s2);    g_E2bo[i] = expf(0.2f * s2);
    }
}

// ---------------- K5: layer-2 aggregation, double-buffered ----------------
// grid (32 i-tiles x 8 j-splits), 256 threads. Warp w: rows w*16. j-range 512, chunk 64.
__global__ __launch_bounds__(256) void k5_mma() {
    __shared__ __align__(16) char Bsm[2][9216];
    __shared__ float scS[2][192];
    uint32_t Bb = s2u(Bsm), scb = s2u(scS);
    int t = threadIdx.x, w = t >> 5, l = t & 31;
    int i0 = blockIdx.x * 128, jbeg = blockIdx.y * 512;
    int rq = w * 16 + (l >> 2);        // local row 0..127
    int jb = 2 * (l & 3);
    int g = l >> 3;

    float s1r[2], E1r[2], E1br[2];
#pragma unroll
    for (int r = 0; r < 2; r++) {
        int gidx = i0 + rq + r * 8;
        s1r[r] = g_s1o[gidx]; E1r[r] = g_E1o[gidx]; E1br[r] = g_E1bo[gidx];
    }
    float den[2] = {};
    float c[8][4] = {};

    auto issue = [&](int buf, int jc) {
#pragma unroll
        for (int p = 0; p < 2; p++) {
            int idx = p * 256 + t;
            int j = idx >> 3, q = idx & 7;
            cpa16(Bb + buf * 9216 + j * 144 + q * 16,
                  g_H2f16 + (size_t)(jc + j) * 64 + q * 8);
        }
        if (t < 192) {
            int type = t >> 6, j = t & 63;
            const float* src = (type == 0) ? g_s2o : (type == 1 ? g_E2o : g_E2bo);
            cpa4(scb + buf * 768 + t * 4, src + jc + j);
        }
    };
    issue(0, jbeg);      CP_COMMIT();
    issue(1, jbeg + 64); CP_COMMIT();

    for (int s = 0; s < 8; s++) {
        int jc = jbeg + s * 64, buf = s & 1;
        CP_WAIT1();
        __syncthreads();

        const float* sc = scS[buf];
        uint32_t awv[2][2];
        {
            uint2 a0 = *(const uint2*)&g_adjbits[(size_t)(i0 + rq) * 128 + (jc >> 5)];
            uint2 a1 = *(const uint2*)&g_adjbits[(size_t)(i0 + rq + 8) * 128 + (jc >> 5)];
            awv[0][0] = a0.x; awv[0][1] = a0.y;
            awv[1][0] = a1.x; awv[1][1] = a1.y;
        }
        uint32_t Bb2 = Bb + buf * 9216;
#pragma unroll
        for (int ks = 0; ks < 4; ks++) {
            float wv[2][4];
#pragma unroll
            for (int q = 0; q < 4; q++) {
                int jl = ks * 16 + jb + (q >> 1) * 8 + (q & 1);
                float s2v = sc[jl], E2v = sc[64 + jl], E2bv = sc[128 + jl];
                int word = ks >> 1, bit = jl & 31;
#pragma unroll
                for (int r = 0; r < 2; r++) {
                    bool pp = (s1r[r] + s2v) >= 0.f;
                    float wt = pp ? E1r[r] * E2v : E1br[r] * E2bv;
                    wt = ((awv[r][word] >> bit) & 1u) ? wt : 0.f;
                    den[r] += wt;
                    wv[r][q] = wt;
                }
            }
            uint32_t bq[8][2];
#pragma unroll
            for (int p = 0; p < 4; p++) {
                uint32_t addr = Bb2 + (ks * 16 + (g & 1) * 8 + (l & 7)) * 144
                              + (p * 2 + (g >> 1)) * 16;
                LDSM_X4T(bq[p * 2][0], bq[p * 2][1], bq[p * 2 + 1][0], bq[p * 2 + 1][1], addr);
            }
            uint32_t a0 = packh2(wv[0][0], wv[0][1]);
            uint32_t a1 = packh2(wv[1][0], wv[1][1]);
            uint32_t a2 = packh2(wv[0][2], wv[0][3]);
            uint32_t a3 = packh2(wv[1][2], wv[1][3]);
#pragma unroll
            for (int nt = 0; nt < 8; nt++)
                mma16816(c[nt], a0, a1, a2, a3, bq[nt][0], bq[nt][1]);
        }
        __syncthreads();
        if (s < 6) issue(buf, jc + 128);
        CP_COMMIT();
    }

#pragma unroll
    for (int r = 0; r < 2; r++) {
        den[r] += __shfl_xor_sync(0xffffffffu, den[r], 1);
        den[r] += __shfl_xor_sync(0xffffffffu, den[r], 2);
    }
    if ((l & 3) == 0) {
        atomicAdd(&g_den2[i0 + rq], den[0]);
        atomicAdd(&g_den2[i0 + rq + 8], den[1]);
    }
#pragma unroll
    for (int nt = 0; nt < 7; nt++) {
        int col = nt * 8 + jb;
        atomicAdd(&g_num2[(size_t)(i0 + rq) * NOUT + col], c[nt][0]);
        atomicAdd(&g_num2[(size_t)(i0 + rq) * NOUT + col + 1], c[nt][1]);
        atomicAdd(&g_num2[(size_t)(i0 + rq + 8) * NOUT + col], c[nt][2]);
        atomicAdd(&g_num2[(size_t)(i0 + rq + 8) * NOUT + col + 1], c[nt][3]);
    }
}

// ---------------- K6: out = softmax(elu(num2/den2)) ----------------
__global__ __launch_bounds__(256) void k6_final(float* __restrict__ out) {
    int wid = (blockIdx.x * 256 + threadIdx.x) >> 5;
    int lane = threadIdx.x & 31;
    if (wid >= N) return;
    float invd = 1.0f / g_den2[wid];
    float v1 = g_num2[(size_t)wid * NOUT + lane] * invd;
    v1 = (v1 > 0.f) ? v1 : expm1f(v1);
    float v2 = -1e30f;
    if (lane < 24) {
        v2 = g_num2[(size_t)wid * NOUT + 32 + lane] * invd;
        v2 = (v2 > 0.f) ? v2 : expm1f(v2);
    }
    float m = fmaxf(v1, v2);
#pragma unroll
    for (int o = 16; o > 0; o >>= 1) m = fmaxf(m, __shfl_xor_sync(0xffffffffu, m, o));
    float e1 = expf(v1 - m);
    float e2 = (lane < 24) ? expf(v2 - m) : 0.f;
    float s = e1 + e2;
#pragma unroll
    for (int o = 16; o > 0; o >>= 1) s += __shfl_xor_sync(0xffffffffu, s, o);
    float invs = 1.0f / s;
    out[(size_t)wid * NOUT + lane] = e1 * invs;
    if (lane < 24) out[(size_t)wid * NOUT + 32 + lane] = e2 * invs;
}

// ---------------- launch ----------------
extern "C" void kernel_launch(void* const* d_in, const int* in_sizes, int n_in,
                              void* d_out, int out_size) {
    (void)in_sizes; (void)n_in; (void)out_size;
    const float* x     = (const float*)d_in[0];
    const int*   adj   = (const int*)d_in[1];
    const float* Ws    = (const float*)d_in[2];
    const float* As_   = (const float*)d_in[3];
    const float* W_out = (const float*)d_in[4];
    const float* a_out = (const float*)d_in[5];
    float* out = (float*)d_out;

    kA_init<<<2048, 256>>>(x, Ws, adj);
    k1_mma<<<dim3(32, 8), 256>>>(As_);
    k3_mma<<<dim3(64, 4), 256>>>();
    k4_h2<<<64, 256>>>(W_out, a_out);
    k5_mma<<<dim3(32, 8), 256>>>();
    k6_final<<<512, 256>>>(out);
}

// round 5
// speedup vs baseline: 7.1817x; 1.2233x over previous
#include <cuda_runtime.h>
#include <cuda_fp16.h>
#include <math.h>
#include <stdint.h>

#define N 4096
#define NHEADS 8
#define NHID 64
#define NFEAT 512
#define NOUT 56

// ---------------- device scratch ----------------
__device__ __half g_xh[(size_t)N * NFEAT];
__device__ __half g_Wh[(size_t)NHEADS * NFEAT * NHID];
__device__ __half g_Hf16[(size_t)NHEADS * N * NHID];
__device__ uint32_t g_adjbits[(size_t)N * 128];
__device__ float g_E1[NHEADS * N], g_E1b[NHEADS * N];
__device__ float g_E2[NHEADS * N], g_E2b[NHEADS * N];
__device__ float g_Z[N * NHID];
__device__ __half g_H2f16[(size_t)N * 64];
__device__ float g_E1o[N], g_E1bo[N], g_E2o[N], g_E2bo[N];
__device__ float g_num2[N * NOUT];
__device__ float g_den2[N];

// ---------------- helpers ----------------
__device__ __forceinline__ uint32_t s2u(const void* p) {
    uint32_t a;
    asm("{ .reg .u64 t; cvta.to.shared.u64 t, %1; cvt.u32.u64 %0, t; }" : "=r"(a) : "l"(p));
    return a;
}
#define LDSM_X4(r0, r1, r2, r3, a) \
    asm volatile("ldmatrix.sync.aligned.m8n8.x4.shared.b16 {%0,%1,%2,%3}, [%4];" \
                 : "=r"(r0), "=r"(r1), "=r"(r2), "=r"(r3) : "r"(a))
#define LDSM_X4T(r0, r1, r2, r3, a) \
    asm volatile("ldmatrix.sync.aligned.m8n8.x4.trans.shared.b16 {%0,%1,%2,%3}, [%4];" \
                 : "=r"(r0), "=r"(r1), "=r"(r2), "=r"(r3) : "r"(a))

__device__ __forceinline__ void mma16816(float* c, uint32_t a0, uint32_t a1, uint32_t a2,
                                         uint32_t a3, uint32_t b0, uint32_t b1) {
    asm volatile(
        "mma.sync.aligned.m16n8k16.row.col.f32.f16.f16.f32 "
        "{%0,%1,%2,%3}, {%4,%5,%6,%7}, {%8,%9}, {%0,%1,%2,%3};"
        : "+f"(c[0]), "+f"(c[1]), "+f"(c[2]), "+f"(c[3])
        : "r"(a0), "r"(a1), "r"(a2), "r"(a3), "r"(b0), "r"(b1));
}
__device__ __forceinline__ uint32_t packh2(float lo, float hi) {
    __half2 h = __floats2half2_rn(lo, hi);
    return *(uint32_t*)&h;
}
__device__ __forceinline__ void cpa16(uint32_t dst, const void* src) {
    asm volatile("cp.async.cg.shared.global [%0], [%1], 16;" :: "r"(dst), "l"(src));
}
__device__ __forceinline__ void cpa4(uint32_t dst, const void* src) {
    asm volatile("cp.async.ca.shared.global [%0], [%1], 4;" :: "r"(dst), "l"(src));
}
#define CP_COMMIT() asm volatile("cp.async.commit_group;")
#define CP_WAIT1()  asm volatile("cp.async.wait_group 1;")
#define CP_WAIT0()  asm volatile("cp.async.wait_group 0;")

// ---------------- KA: merged init ----------------
__global__ __launch_bounds__(256) void kA_init(const float* __restrict__ x,
                                               const float* __restrict__ Ws,
                                               const int* __restrict__ adj) {
    int t = threadIdx.x;
    int gid = blockIdx.x * 256 + t;
    int stride = gridDim.x * 256;
    int w = gid >> 5, lane = t & 31;
    int row = w >> 2, quarter = w & 3;
    size_t base = (size_t)row * N + quarter * 1024;
#pragma unroll 4
    for (int it = 0; it < 32; it++) {
        int v = adj[base + it * 32 + lane];
        uint32_t m = __ballot_sync(0xffffffffu, v > 0);
        if (lane == 0) g_adjbits[(size_t)row * 128 + quarter * 32 + it] = m;
    }
    for (int i = gid; i < N * NFEAT / 2; i += stride) {
        float2 v = ((const float2*)x)[i];
        ((__half2*)g_xh)[i] = __floats2half2_rn(v.x, v.y);
    }
    for (int i = gid; i < NHEADS * NFEAT * NHID / 2; i += stride) {
        float2 v = ((const float2*)Ws)[i];
        ((__half2*)g_Wh)[i] = __floats2half2_rn(v.x, v.y);
    }
    for (int i = gid; i < N * NHID; i += stride) g_Z[i] = 0.f;
    for (int i = gid; i < N * NOUT; i += stride) g_num2[i] = 0.f;
    for (int i = gid; i < N; i += stride) g_den2[i] = 0.f;
}

// ---------------- K1: H = x @ Ws via fp16 mma, cp.async 2-stage, fused exp epilogue ----------------
#define K1_AS 80
#define K1_BS 144
__global__ __launch_bounds__(256) void k1_mma(const float* __restrict__ As_) {
    __shared__ __align__(16) char Asm[2][128 * K1_AS];
    __shared__ __align__(16) char Bsm[2][32 * K1_BS];
    __shared__ __align__(16) __half Hsm[128 * 64];
    uint32_t Abase = s2u(Asm), Bbase = s2u(Bsm);
    int t = threadIdx.x, w = t >> 5, l = t & 31;
    int i0 = blockIdx.x * 128;
    int h = blockIdx.y;
    int rbase = (w & 3) * 32;
    int ntb = (w >> 2) * 4;
    float c[2][4][4] = {};
    const __half* wsrc = g_Wh + (size_t)h * NFEAT * NHID;

    auto issue = [&](int buf, int kc) {
#pragma unroll
        for (int p = 0; p < 2; p++) {
            int idx = p * 256 + t;
            int rr = idx >> 2, q = idx & 3;
            cpa16(Abase + buf * (128 * K1_AS) + rr * K1_AS + q * 16,
                  g_xh + (size_t)(i0 + rr) * NFEAT + kc + q * 8);
        }
        {
            int rr = t >> 3, q = t & 7;
            cpa16(Bbase + buf * (32 * K1_BS) + rr * K1_BS + q * 16,
                  wsrc + (size_t)(kc + rr) * NHID + q * 8);
        }
    };
    issue(0, 0); CP_COMMIT();

    for (int s = 0; s < 16; s++) {
        if (s < 15) { issue((s + 1) & 1, (s + 1) * 32); CP_COMMIT(); CP_WAIT1(); }
        else CP_WAIT0();
        __syncthreads();
        int buf = s & 1;
        uint32_t Ab2 = Abase + buf * (128 * K1_AS);
        uint32_t Bb2 = Bbase + buf * (32 * K1_BS);
        int g = l >> 3;
#pragma unroll
        for (int ks = 0; ks < 2; ks++) {
            uint32_t bq[4][2];
#pragma unroll
            for (int p = 0; p < 2; p++) {
                uint32_t addr = Bb2 + (ks * 16 + (g & 1) * 8 + (l & 7)) * K1_BS
                              + (ntb + p * 2 + (g >> 1)) * 16;
                LDSM_X4T(bq[p * 2][0], bq[p * 2][1], bq[p * 2 + 1][0], bq[p * 2 + 1][1], addr);
            }
#pragma unroll
            for (int rf = 0; rf < 2; rf++) {
                uint32_t a0, a1, a2, a3;
                uint32_t addr = Ab2 + (rbase + rf * 16 + (g & 1) * 8 + (l & 7)) * K1_AS
                              + (ks * 16 + (g >> 1) * 8) * 2;
                LDSM_X4(a0, a1, a2, a3, addr);
#pragma unroll
                for (int nt = 0; nt < 4; nt++)
                    mma16816(c[rf][nt], a0, a1, a2, a3, bq[nt][0], bq[nt][1]);
            }
        }
        __syncthreads();
    }
    __half* dst = g_Hf16 + (size_t)h * N * NHID;
#pragma unroll
    for (int rf = 0; rf < 2; rf++)
#pragma unroll
        for (int nt = 0; nt < 4; nt++) {
            int rl = rbase + rf * 16 + (l >> 2);
            int col = (ntb + nt) * 8 + 2 * (l & 3);
            uint32_t v01 = packh2(c[rf][nt][0], c[rf][nt][1]);
            uint32_t v23 = packh2(c[rf][nt][2], c[rf][nt][3]);
            *(uint32_t*)(dst + (size_t)(i0 + rl) * 64 + col) = v01;
            *(uint32_t*)(dst + (size_t)(i0 + rl + 8) * 64 + col) = v23;
            *(uint32_t*)(Hsm + rl * 64 + col) = v01;
            *(uint32_t*)(Hsm + (rl + 8) * 64 + col) = v23;
        }
    __syncthreads();

    float a1lo = As_[h * 128 + 2 * l], a1hi = As_[h * 128 + 2 * l + 1];
    float a2lo = As_[h * 128 + 64 + 2 * l], a2hi = As_[h * 128 + 64 + 2 * l + 1];
    for (int rr = 0; rr < 16; rr++) {
        int rl = w * 16 + rr;
        __half2 hv = ((__half2*)(Hsm + rl * 64))[l];
        float xl = __low2float(hv), xh = __high2float(hv);
        float s1p = xl * a1lo + xh * a1hi;
        float s2p = xl * a2lo + xh * a2hi;
#pragma unroll
        for (int o = 16; o > 0; o >>= 1) {
            s1p += __shfl_xor_sync(0xffffffffu, s1p, o);
            s2p += __shfl_xor_sync(0xffffffffu, s2p, o);
        }
        if (l == 0) {
            int idx = h * N + i0 + rl;
            g_E1[idx] = expf(s1p);  g_E1b[idx] = expf(0.2f * s1p);
            g_E2[idx] = expf(s2p);  g_E2b[idx] = expf(0.2f * s2p);
        }
    }
}

// ---------------- K3: layer-1 aggregation, 3-stage pipeline, max-trick gen ----------------
// dyn smem: B [3][2][9216] = 55296, scS [3][256]f = 3072, dens 128f = 512  -> 58880
#define K3_BBYTES 18432
#define K3_SMEM (55296 + 3072 + 512)
__global__ __launch_bounds__(256, 2) void k3_mma() {
    extern __shared__ __align__(16) char dsm[];
    uint32_t Bb = s2u(dsm);
    float* scS = (float*)(dsm + 55296);
    uint32_t scb = s2u(scS);
    float* dens = (float*)(dsm + 55296 + 3072);

    int t = threadIdx.x, w = t >> 5, l = t & 31;
    int i0 = blockIdx.x * 64, h0 = blockIdx.y * 2;
    int hh = w >> 2;
    int rq = (w & 3) * 16 + (l >> 2);
    int jb = 2 * (l & 3);
    int g = l >> 3;

    float E1r[2], E1br[2];
#pragma unroll
    for (int r = 0; r < 2; r++) {
        int gidx = (h0 + hh) * N + i0 + rq + r * 8;
        E1r[r] = g_E1[gidx]; E1br[r] = g_E1b[gidx];
    }
    float den[2] = {};
    float c[8][4] = {};

    auto issue = [&](int buf, int jc) {
#pragma unroll
        for (int p = 0; p < 4; p++) {
            int idx = p * 256 + t;
            int bh = idx >> 9, rem = idx & 511, j = rem >> 3, q = rem & 7;
            cpa16(Bb + buf * K3_BBYTES + bh * 9216 + j * 144 + q * 16,
                  g_Hf16 + ((size_t)(h0 + bh) * N + jc + j) * 64 + q * 8);
        }
        {
            int bh = t >> 7, rem = t & 127, type = rem >> 6, j = rem & 63;
            const float* src = type ? g_E2b : g_E2;
            cpa4(scb + buf * 1024 + t * 4, src + (h0 + bh) * N + jc + j);
        }
    };
    issue(0, 0);  CP_COMMIT();
    issue(1, 64); CP_COMMIT();

    for (int s = 0; s < 64; s++) {
        int jc = s * 64, buf = s - (s / 3) * 3;
        CP_WAIT1();
        __syncthreads();
        if (s < 62) issue((s + 2) - ((s + 2) / 3) * 3, jc + 128);
        CP_COMMIT();

        const float* sc = scS + buf * 256 + hh * 128;
        uint32_t awv[2][2];
        {
            uint2 a0 = *(const uint2*)&g_adjbits[(size_t)(i0 + rq) * 128 + (jc >> 5)];
            uint2 a1 = *(const uint2*)&g_adjbits[(size_t)(i0 + rq + 8) * 128 + (jc >> 5)];
            awv[0][0] = a0.x; awv[0][1] = a0.y;
            awv[1][0] = a1.x; awv[1][1] = a1.y;
        }
        uint32_t Bb2 = Bb + buf * K3_BBYTES + hh * 9216;
#pragma unroll
        for (int ks = 0; ks < 4; ks++) {
            uint32_t m0 = awv[0][ks >> 1] >> ((ks & 1) * 16 + jb);
            uint32_t m1 = awv[1][ks >> 1] >> ((ks & 1) * 16 + jb);
            float wv[2][4];
#pragma unroll
            for (int q = 0; q < 4; q++) {
                int jl = ks * 16 + jb + (q >> 1) * 8 + (q & 1);
                float E2v = sc[jl], E2bv = sc[64 + jl];
                const int cb = (q >> 1) * 8 + (q & 1);
                float w0 = fmaxf(E1r[0] * E2v, E1br[0] * E2bv);
                float w1 = fmaxf(E1r[1] * E2v, E1br[1] * E2bv);
                w0 = ((m0 >> cb) & 1u) ? w0 : 0.f;
                w1 = ((m1 >> cb) & 1u) ? w1 : 0.f;
                den[0] += w0; den[1] += w1;
                wv[0][q] = w0; wv[1][q] = w1;
            }
            uint32_t bq[8][2];
#pragma unroll
            for (int p = 0; p < 4; p++) {
                uint32_t addr = Bb2 + (ks * 16 + (g & 1) * 8 + (l & 7)) * 144
                              + (p * 2 + (g >> 1)) * 16;
                LDSM_X4T(bq[p * 2][0], bq[p * 2][1], bq[p * 2 + 1][0], bq[p * 2 + 1][1], addr);
            }
            uint32_t a0 = packh2(wv[0][0], wv[0][1]);
            uint32_t a1 = packh2(wv[1][0], wv[1][1]);
            uint32_t a2 = packh2(wv[0][2], wv[0][3]);
            uint32_t a3 = packh2(wv[1][2], wv[1][3]);
#pragma unroll
            for (int nt = 0; nt < 8; nt++)
                mma16816(c[nt], a0, a1, a2, a3, bq[nt][0], bq[nt][1]);
        }
    }

#pragma unroll
    for (int r = 0; r < 2; r++) {
        den[r] += __shfl_xor_sync(0xffffffffu, den[r], 1);
        den[r] += __shfl_xor_sync(0xffffffffu, den[r], 2);
    }
    __syncthreads();
    if ((l & 3) == 0) {
        dens[hh * 64 + rq] = den[0];
        dens[hh * 64 + rq + 8] = den[1];
    }
    __syncthreads();

    float inv0 = 1.f / dens[hh * 64 + rq];
    float inv1 = 1.f / dens[hh * 64 + rq + 8];
#pragma unroll
    for (int nt = 0; nt < 8; nt++) {
        int col = nt * 8 + jb;
        float v;
        v = c[nt][0] * inv0; v = (v > 0.f) ? v : expm1f(v);
        atomicAdd(&g_Z[(size_t)(i0 + rq) * 64 + col], 0.125f * v);
        v = c[nt][1] * inv0; v = (v > 0.f) ? v : expm1f(v);
        atomicAdd(&g_Z[(size_t)(i0 + rq) * 64 + col + 1], 0.125f * v);
        v = c[nt][2] * inv1; v = (v > 0.f) ? v : expm1f(v);
        atomicAdd(&g_Z[(size_t)(i0 + rq + 8) * 64 + col], 0.125f * v);
        v = c[nt][3] * inv1; v = (v > 0.f) ? v : expm1f(v);
        atomicAdd(&g_Z[(size_t)(i0 + rq + 8) * 64 + col + 1], 0.125f * v);
    }
}

// ---------------- K4: h2 = z @ W_out (grid 256, 16 rows/CTA) ----------------
__global__ __launch_bounds__(256) void k4_h2(const float* __restrict__ W_out,
                                             const float* __restrict__ a_out) {
    __shared__ float Wo[64 * 56];
    __shared__ float ao[112];
    __shared__ float zs[16 * 64];
    __shared__ float h2s[16 * 56];
    int t = threadIdx.x, w = t >> 5, l = t & 31;
    int i0 = blockIdx.x * 16;
    for (int idx = t; idx < 64 * 56; idx += 256) Wo[idx] = W_out[idx];
    if (t < 112) ao[t] = a_out[t];
    *(float4*)&zs[t * 4] = *(const float4*)&g_Z[(size_t)(i0 + (t >> 4)) * 64 + (t & 15) * 4];
    __syncthreads();
#pragma unroll
    for (int e = 0; e < 4; e++) {
        int idx = e * 256 + t;
        if (idx < 16 * 56) {
            int i = idx / 56, cc = idx % 56;
            float s = 0.f;
#pragma unroll
            for (int k = 0; k < 64; k++) s = fmaf(zs[i * 64 + k], Wo[k * 56 + cc], s);
            h2s[idx] = s;
            g_H2f16[(size_t)(i0 + i) * 64 + cc] = __float2half(s);
        }
    }
    if (t < 128)
        g_H2f16[(size_t)(i0 + (t >> 3)) * 64 + 56 + (t & 7)] = __float2half(0.f);
    __syncthreads();
#pragma unroll
    for (int rr = 0; rr < 2; rr++) {
        int row = w * 2 + rr;
        float v1 = h2s[row * 56 + l];
        float v2 = (l < 24) ? h2s[row * 56 + 32 + l] : 0.f;
        float s1 = v1 * ao[l] + ((l < 24) ? v2 * ao[32 + l] : 0.f);
        float s2 = v1 * ao[56 + l] + ((l < 24) ? v2 * ao[88 + l] : 0.f);
#pragma unroll
        for (int o = 16; o > 0; o >>= 1) {
            s1 += __shfl_xor_sync(0xffffffffu, s1, o);
            s2 += __shfl_xor_sync(0xffffffffu, s2, o);
        }
        if (l == 0) {
            int i = i0 + row;
            g_E1o[i] = expf(s1);    g_E1bo[i] = expf(0.2f * s1);
            g_E2o[i] = expf(s2);    g_E2bo[i] = expf(0.2f * s2);
        }
    }
}

// ---------------- K5: layer-2 aggregation, 3-stage pipeline ----------------
__global__ __launch_bounds__(256, 2) void k5_mma() {
    __shared__ __align__(16) char Bsm[3][9216];
    __shared__ float scS[3][128];
    uint32_t Bb = s2u(Bsm), scb = s2u(scS);
    int t = threadIdx.x, w = t >> 5, l = t & 31;
    int i0 = blockIdx.x * 128, jbeg = blockIdx.y * 512;
    int rq = w * 16 + (l >> 2);
    int jb = 2 * (l & 3);
    int g = l >> 3;

    float E1r[2], E1br[2];
#pragma unroll
    for (int r = 0; r < 2; r++) {
        int gidx = i0 + rq + r * 8;
        E1r[r] = g_E1o[gidx]; E1br[r] = g_E1bo[gidx];
    }
    float den[2] = {};
    float c[8][4] = {};

    auto issue = [&](int buf, int jc) {
#pragma unroll
        for (int p = 0; p < 2; p++) {
            int idx = p * 256 + t;
            int j = idx >> 3, q = idx & 7;
            cpa16(Bb + buf * 9216 + j * 144 + q * 16,
                  g_H2f16 + (size_t)(jc + j) * 64 + q * 8);
        }
        if (t < 128) {
            int type = t >> 6, j = t & 63;
            const float* src = type ? g_E2bo : g_E2o;
            cpa4(scb + buf * 512 + t * 4, src + jc + j);
        }
    };
    issue(0, jbeg);      CP_COMMIT();
    issue(1, jbeg + 64); CP_COMMIT();

    for (int s = 0; s < 8; s++) {
        int jc = jbeg + s * 64, buf = s - (s / 3) * 3;
        CP_WAIT1();
        __syncthreads();
        if (s < 6) issue((s + 2) - ((s + 2) / 3) * 3, jc + 128);
        CP_COMMIT();

        const float* sc = scS[buf];
        uint32_t awv[2][2];
        {
            uint2 a0 = *(const uint2*)&g_adjbits[(size_t)(i0 + rq) * 128 + (jc >> 5)];
            uint2 a1 = *(const uint2*)&g_adjbits[(size_t)(i0 + rq + 8) * 128 + (jc >> 5)];
            awv[0][0] = a0.x; awv[0][1] = a0.y;
            awv[1][0] = a1.x; awv[1][1] = a1.y;
        }
        uint32_t Bb2 = Bb + buf * 9216;
#pragma unroll
        for (int ks = 0; ks < 4; ks++) {
            uint32_t m0 = awv[0][ks >> 1] >> ((ks & 1) * 16 + jb);
            uint32_t m1 = awv[1][ks >> 1] >> ((ks & 1) * 16 + jb);
            float wv[2][4];
#pragma unroll
            for (int q = 0; q < 4; q++) {
                int jl = ks * 16 + jb + (q >> 1) * 8 + (q & 1);
                float E2v = sc[jl], E2bv = sc[64 + jl];
                const int cb = (q >> 1) * 8 + (q & 1);
                float w0 = fmaxf(E1r[0] * E2v, E1br[0] * E2bv);
                float w1 = fmaxf(E1r[1] * E2v, E1br[1] * E2bv);
                w0 = ((m0 >> cb) & 1u) ? w0 : 0.f;
                w1 = ((m1 >> cb) & 1u) ? w1 : 0.f;
                den[0] += w0; den[1] += w1;
                wv[0][q] = w0; wv[1][q] = w1;
            }
            uint32_t bq[8][2];
#pragma unroll
            for (int p = 0; p < 4; p++) {
                uint32_t addr = Bb2 + (ks * 16 + (g & 1) * 8 + (l & 7)) * 144
                              + (p * 2 + (g >> 1)) * 16;
                LDSM_X4T(bq[p * 2][0], bq[p * 2][1], bq[p * 2 + 1][0], bq[p * 2 + 1][1], addr);
            }
            uint32_t a0 = packh2(wv[0][0], wv[0][1]);
            uint32_t a1 = packh2(wv[1][0], wv[1][1]);
            uint32_t a2 = packh2(wv[0][2], wv[0][3]);
            uint32_t a3 = packh2(wv[1][2], wv[1][3]);
#pragma unroll
            for (int nt = 0; nt < 8; nt++)
                mma16816(c[nt], a0, a1, a2, a3, bq[nt][0], bq[nt][1]);
        }
    }

#pragma unroll
    for (int r = 0; r < 2; r++) {
        den[r] += __shfl_xor_sync(0xffffffffu, den[r], 1);
        den[r] += __shfl_xor_sync(0xffffffffu, den[r], 2);
    }
    if ((l & 3) == 0) {
        atomicAdd(&g_den2[i0 + rq], den[0]);
        atomicAdd(&g_den2[i0 + rq + 8], den[1]);
    }
#pragma unroll
    for (int nt = 0; nt < 7; nt++) {
        int col = nt * 8 + jb;
        atomicAdd(&g_num2[(size_t)(i0 + rq) * NOUT + col], c[nt][0]);
        atomicAdd(&g_num2[(size_t)(i0 + rq) * NOUT + col + 1], c[nt][1]);
        atomicAdd(&g_num2[(size_t)(i0 + rq + 8) * NOUT + col], c[nt][2]);
        atomicAdd(&g_num2[(size_t)(i0 + rq + 8) * NOUT + col + 1], c[nt][3]);
    }
}

// ---------------- K6: out = softmax(elu(num2/den2)) ----------------
__global__ __launch_bounds__(256) void k6_final(float* __restrict__ out) {
    int wid = (blockIdx.x * 256 + threadIdx.x) >> 5;
    int lane = threadIdx.x & 31;
    if (wid >= N) return;
    float invd = 1.0f / g_den2[wid];
    float v1 = g_num2[(size_t)wid * NOUT + lane] * invd;
    v1 = (v1 > 0.f) ? v1 : expm1f(v1);
    float v2 = -1e30f;
    if (lane < 24) {
        v2 = g_num2[(size_t)wid * NOUT + 32 + lane] * invd;
        v2 = (v2 > 0.f) ? v2 : expm1f(v2);
    }
    float m = fmaxf(v1, v2);
#pragma unroll
    for (int o = 16; o > 0; o >>= 1) m = fmaxf(m, __shfl_xor_sync(0xffffffffu, m, o));
    float e1 = expf(v1 - m);
    float e2 = (lane < 24) ? expf(v2 - m) : 0.f;
    float s = e1 + e2;
#pragma unroll
    for (int o = 16; o > 0; o >>= 1) s += __shfl_xor_sync(0xffffffffu, s, o);
    float invs = 1.0f / s;
    out[(size_t)wid * NOUT + lane] = e1 * invs;
    if (lane < 24) out[(size_t)wid * NOUT + 32 + lane] = e2 * invs;
}

// ---------------- launch ----------------
extern "C" void kernel_launch(void* const* d_in, const int* in_sizes, int n_in,
                              void* d_out, int out_size) {
    (void)in_sizes; (void)n_in; (void)out_size;
    const float* x     = (const float*)d_in[0];
    const int*   adj   = (const int*)d_in[1];
    const float* Ws    = (const float*)d_in[2];
    const float* As_   = (const float*)d_in[3];
    const float* W_out = (const float*)d_in[4];
    const float* a_out = (const float*)d_in[5];
    float* out = (float*)d_out;

    cudaFuncSetAttribute(k3_mma, cudaFuncAttributeMaxDynamicSharedMemorySize, K3_SMEM);

    kA_init<<<2048, 256>>>(x, Ws, adj);
    k1_mma<<<dim3(32, 8), 256>>>(As_);
    k3_mma<<<dim3(64, 4), 256, K3_SMEM>>>();
    k4_h2<<<256, 256>>>(W_out, a_out);
    k5_mma<<<dim3(32, 8), 256>>>();
    k6_final<<<512, 256>>>(out);
}

// round 6
// speedup vs baseline: 7.6570x; 1.0662x over previous
#include <cuda_runtime.h>
#include <cuda_fp16.h>
#include <math.h>
#include <stdint.h>

#define N 4096
#define NHEADS 8
#define NHID 64
#define NFEAT 512
#define NOUT 56

// ---------------- device scratch ----------------
__device__ __half g_xh[(size_t)N * NFEAT];
__device__ __half g_Wh[(size_t)NHEADS * NFEAT * NHID];
__device__ __half g_Hf16[(size_t)NHEADS * N * NHID];
__device__ uint32_t g_adjbits[(size_t)N * 128];
__device__ __half g_E1h[NHEADS * N], g_E1bh[NHEADS * N];
__device__ __half g_E2h[NHEADS * N], g_E2bh[NHEADS * N];
__device__ float g_Z[N * NHID];
__device__ __half g_H2f16[(size_t)N * 64];   // col 56 = 1.0 (den trick), 57-63 = 0
__device__ __half g_E1oh[N], g_E1boh[N], g_E2oh[N], g_E2boh[N];
__device__ float g_num2[N * NOUT];
__device__ float g_den2[N];

// ---------------- helpers ----------------
__device__ __forceinline__ uint32_t s2u(const void* p) {
    uint32_t a;
    asm("{ .reg .u64 t; cvta.to.shared.u64 t, %1; cvt.u32.u64 %0, t; }" : "=r"(a) : "l"(p));
    return a;
}
#define LDSM_X4(r0, r1, r2, r3, a) \
    asm volatile("ldmatrix.sync.aligned.m8n8.x4.shared.b16 {%0,%1,%2,%3}, [%4];" \
                 : "=r"(r0), "=r"(r1), "=r"(r2), "=r"(r3) : "r"(a))
#define LDSM_X4T(r0, r1, r2, r3, a) \
    asm volatile("ldmatrix.sync.aligned.m8n8.x4.trans.shared.b16 {%0,%1,%2,%3}, [%4];" \
                 : "=r"(r0), "=r"(r1), "=r"(r2), "=r"(r3) : "r"(a))

__device__ __forceinline__ void mma16816(float* c, uint32_t a0, uint32_t a1, uint32_t a2,
                                         uint32_t a3, uint32_t b0, uint32_t b1) {
    asm volatile(
        "mma.sync.aligned.m16n8k16.row.col.f32.f16.f16.f32 "
        "{%0,%1,%2,%3}, {%4,%5,%6,%7}, {%8,%9}, {%0,%1,%2,%3};"
        : "+f"(c[0]), "+f"(c[1]), "+f"(c[2]), "+f"(c[3])
        : "r"(a0), "r"(a1), "r"(a2), "r"(a3), "r"(b0), "r"(b1));
}
__device__ __forceinline__ uint32_t packh2(float lo, float hi) {
    __half2 h = __floats2half2_rn(lo, hi);
    return *(uint32_t*)&h;
}
__device__ __forceinline__ uint32_t h2u(__half2 h) { return *(uint32_t*)&h; }
__device__ __forceinline__ void cpa16(uint32_t dst, const void* src) {
    asm volatile("cp.async.cg.shared.global [%0], [%1], 16;" :: "r"(dst), "l"(src));
}
__device__ __forceinline__ void cpa4(uint32_t dst, const void* src) {
    asm volatile("cp.async.ca.shared.global [%0], [%1], 4;" :: "r"(dst), "l"(src));
}
#define CP_COMMIT() asm volatile("cp.async.commit_group;")
#define CP_WAIT1()  asm volatile("cp.async.wait_group 1;")
#define CP_WAIT0()  asm volatile("cp.async.wait_group 0;")

// ---------------- KA: merged init ----------------
__global__ __launch_bounds__(256) void kA_init(const float* __restrict__ x,
                                               const float* __restrict__ Ws,
                                               const int* __restrict__ adj) {
    int t = threadIdx.x;
    int gid = blockIdx.x * 256 + t;
    int stride = gridDim.x * 256;
    int w = gid >> 5, lane = t & 31;
    int row = w >> 2, quarter = w & 3;
    const int4* src = (const int4*)(adj + (size_t)row * N + quarter * 1024);
    uint32_t* dstw = g_adjbits + (size_t)row * 128 + quarter * 32;
#pragma unroll
    for (int it = 0; it < 8; it++) {
        int4 v = src[it * 32 + lane];
        uint32_t nib = (uint32_t)(v.x > 0) | ((uint32_t)(v.y > 0) << 1)
                     | ((uint32_t)(v.z > 0) << 2) | ((uint32_t)(v.w > 0) << 3);
        uint32_t word = nib << (4 * (lane & 7));
        word |= __shfl_xor_sync(0xffffffffu, word, 1);
        word |= __shfl_xor_sync(0xffffffffu, word, 2);
        word |= __shfl_xor_sync(0xffffffffu, word, 4);
        if ((lane & 7) == 0) dstw[it * 4 + (lane >> 3)] = word;
    }
    for (int i = gid; i < N * NFEAT / 2; i += stride) {
        float2 v = ((const float2*)x)[i];
        ((__half2*)g_xh)[i] = __floats2half2_rn(v.x, v.y);
    }
    for (int i = gid; i < NHEADS * NFEAT * NHID / 2; i += stride) {
        float2 v = ((const float2*)Ws)[i];
        ((__half2*)g_Wh)[i] = __floats2half2_rn(v.x, v.y);
    }
    for (int i = gid; i < N * NHID; i += stride) g_Z[i] = 0.f;
    for (int i = gid; i < N * NOUT; i += stride) g_num2[i] = 0.f;
    for (int i = gid; i < N; i += stride) g_den2[i] = 0.f;
}

// ---------------- K1: H = x @ Ws, 64x64 tile, 128 threads, fused exp epilogue ----------------
#define K1_AS 80
#define K1_BS 144
__global__ __launch_bounds__(128) void k1_mma(const float* __restrict__ As_) {
    __shared__ __align__(16) char Asm[2][64 * K1_AS];
    __shared__ __align__(16) char Bsm[2][32 * K1_BS];
    __shared__ __align__(16) __half Hsm[64 * 64];
    uint32_t Abase = s2u(Asm), Bbase = s2u(Bsm);
    int t = threadIdx.x, w = t >> 5, l = t & 31;
    int i0 = blockIdx.x * 64;
    int h = blockIdx.y;
    int rbase = (w & 1) * 32;
    int ntb = (w >> 1) * 4;
    float c[2][4][4] = {};
    const __half* wsrc = g_Wh + (size_t)h * NFEAT * NHID;

    auto issue = [&](int buf, int kc) {
#pragma unroll
        for (int p = 0; p < 2; p++) {
            int idx = p * 128 + t;
            int rr = idx >> 2, q = idx & 3;
            cpa16(Abase + buf * (64 * K1_AS) + rr * K1_AS + q * 16,
                  g_xh + (size_t)(i0 + rr) * NFEAT + kc + q * 8);
        }
#pragma unroll
        for (int p = 0; p < 2; p++) {
            int idx = p * 128 + t;
            int rr = idx >> 3, q = idx & 7;
            cpa16(Bbase + buf * (32 * K1_BS) + rr * K1_BS + q * 16,
                  wsrc + (size_t)(kc + rr) * NHID + q * 8);
        }
    };
    issue(0, 0); CP_COMMIT();

    for (int s = 0; s < 16; s++) {
        if (s < 15) { issue((s + 1) & 1, (s + 1) * 32); CP_COMMIT(); CP_WAIT1(); }
        else CP_WAIT0();
        __syncthreads();
        int buf = s & 1;
        uint32_t Ab2 = Abase + buf * (64 * K1_AS);
        uint32_t Bb2 = Bbase + buf * (32 * K1_BS);
        int g = l >> 3;
#pragma unroll
        for (int ks = 0; ks < 2; ks++) {
            uint32_t bq[4][2];
#pragma unroll
            for (int p = 0; p < 2; p++) {
                uint32_t addr = Bb2 + (ks * 16 + (g & 1) * 8 + (l & 7)) * K1_BS
                              + (ntb + p * 2 + (g >> 1)) * 16;
                LDSM_X4T(bq[p * 2][0], bq[p * 2][1], bq[p * 2 + 1][0], bq[p * 2 + 1][1], addr);
            }
#pragma unroll
            for (int rf = 0; rf < 2; rf++) {
                uint32_t a0, a1, a2, a3;
                uint32_t addr = Ab2 + (rbase + rf * 16 + (g & 1) * 8 + (l & 7)) * K1_AS
                              + (ks * 16 + (g >> 1) * 8) * 2;
                LDSM_X4(a0, a1, a2, a3, addr);
#pragma unroll
                for (int nt = 0; nt < 4; nt++)
                    mma16816(c[rf][nt], a0, a1, a2, a3, bq[nt][0], bq[nt][1]);
            }
        }
        __syncthreads();
    }
    __half* dst = g_Hf16 + (size_t)h * N * NHID;
#pragma unroll
    for (int rf = 0; rf < 2; rf++)
#pragma unroll
        for (int nt = 0; nt < 4; nt++) {
            int rl = rbase + rf * 16 + (l >> 2);
            int col = (ntb + nt) * 8 + 2 * (l & 3);
            uint32_t v01 = packh2(c[rf][nt][0], c[rf][nt][1]);
            uint32_t v23 = packh2(c[rf][nt][2], c[rf][nt][3]);
            *(uint32_t*)(dst + (size_t)(i0 + rl) * 64 + col) = v01;
            *(uint32_t*)(dst + (size_t)(i0 + rl + 8) * 64 + col) = v23;
            *(uint32_t*)(Hsm + rl * 64 + col) = v01;
            *(uint32_t*)(Hsm + (rl + 8) * 64 + col) = v23;
        }
    __syncthreads();

    float a1lo = As_[h * 128 + 2 * l], a1hi = As_[h * 128 + 2 * l + 1];
    float a2lo = As_[h * 128 + 64 + 2 * l], a2hi = As_[h * 128 + 64 + 2 * l + 1];
    for (int rr = 0; rr < 16; rr++) {
        int rl = w * 16 + rr;
        __half2 hv = ((__half2*)(Hsm + rl * 64))[l];
        float xl = __low2float(hv), xh = __high2float(hv);
        float s1p = xl * a1lo + xh * a1hi;
        float s2p = xl * a2lo + xh * a2hi;
#pragma unroll
        for (int o = 16; o > 0; o >>= 1) {
            s1p += __shfl_xor_sync(0xffffffffu, s1p, o);
            s2p += __shfl_xor_sync(0xffffffffu, s2p, o);
        }
        if (l == 0) {
            int idx = h * N + i0 + rl;
            g_E1h[idx]  = __float2half(expf(s1p));
            g_E1bh[idx] = __float2half(expf(0.2f * s1p));
            g_E2h[idx]  = __float2half(expf(s2p));
            g_E2bh[idx] = __float2half(expf(0.2f * s2p));
        }
    }
}

// ---------------- K3: layer-1 aggregation; half2 gen, den via ones-MMA ----------------
#define K3_BBYTES 18432
#define K3_SCOFF 55296
#define K3_SMEM (55296 + 3 * 512)
__global__ __launch_bounds__(256, 2) void k3_mma() {
    extern __shared__ __align__(16) char dsm[];
    __shared__ __half2 mtab[4];
    uint32_t Bb = s2u(dsm);
    uint32_t scb = Bb + K3_SCOFF;

    int t = threadIdx.x, w = t >> 5, l = t & 31;
    int i0 = blockIdx.x * 64, h0 = blockIdx.y * 2;
    int hh = w >> 2;
    int rq = (w & 3) * 16 + (l >> 2);
    int jb = 2 * (l & 3);
    int g = l >> 3;
    if (t < 4) mtab[t] = __floats2half2_rn((t & 1) ? 1.f : 0.f, (t >> 1) ? 1.f : 0.f);

    __half2 E1x2[2], E1bx2[2];
#pragma unroll
    for (int r = 0; r < 2; r++) {
        int gidx = (h0 + hh) * N + i0 + rq + r * 8;
        E1x2[r] = __half2half2(g_E1h[gidx]);
        E1bx2[r] = __half2half2(g_E1bh[gidx]);
    }
    float c[8][4] = {}, cden[4] = {};
    uint32_t ones_b = (l < 4) ? 0x3C003C00u : 0u;

    auto issue = [&](int buf, int jc) {
#pragma unroll
        for (int p = 0; p < 4; p++) {
            int idx = p * 256 + t;
            int bh = idx >> 9, rem = idx & 511, j = rem >> 3, q = rem & 7;
            cpa16(Bb + buf * K3_BBYTES + bh * 9216 + j * 144 + q * 16,
                  g_Hf16 + ((size_t)(h0 + bh) * N + jc + j) * 64 + q * 8);
        }
        if (t < 128) {
            int bh = t >> 6, rem = t & 63, type = rem >> 5, jj = rem & 31;
            const __half* srcp = (type ? g_E2bh : g_E2h) + (size_t)(h0 + bh) * N + jc + jj * 2;
            cpa4(scb + buf * 512 + bh * 256 + type * 128 + jj * 4, srcp);
        }
    };
    issue(0, 0);  CP_COMMIT();
    issue(1, 64); CP_COMMIT();

    for (int s = 0; s < 64; s++) {
        int jc = s * 64, buf = s - (s / 3) * 3;
        CP_WAIT1();
        __syncthreads();
        if (s < 62) issue((s + 2) - ((s + 2) / 3) * 3, jc + 128);
        CP_COMMIT();

        const __half* scE2 = (const __half*)(dsm + K3_SCOFF + buf * 512 + hh * 256);
        uint32_t aw0[2], aw1[2];
        {
            uint2 a0 = *(const uint2*)&g_adjbits[(size_t)(i0 + rq) * 128 + (jc >> 5)];
            uint2 a1 = *(const uint2*)&g_adjbits[(size_t)(i0 + rq + 8) * 128 + (jc >> 5)];
            aw0[0] = a0.x; aw0[1] = a0.y;
            aw1[0] = a1.x; aw1[1] = a1.y;
        }
        uint32_t Bb2 = Bb + buf * K3_BBYTES + hh * 9216;
#pragma unroll
        for (int ks = 0; ks < 4; ks++) {
            uint32_t sh = (ks & 1) * 16 + jb;
            uint32_t m0 = aw0[ks >> 1] >> sh;
            uint32_t m1 = aw1[ks >> 1] >> sh;
            uint32_t areg[4];
#pragma unroll
            for (int p = 0; p < 2; p++) {
                int j0 = ks * 16 + jb + p * 8;
                __half2 e2  = *(const __half2*)(scE2 + j0);
                __half2 e2b = *(const __half2*)(scE2 + 64 + j0);
                __half2 w0 = __hmul2(__hmax2(__hmul2(E1x2[0], e2), __hmul2(E1bx2[0], e2b)),
                                     mtab[(m0 >> (p * 8)) & 3]);
                __half2 w1 = __hmul2(__hmax2(__hmul2(E1x2[1], e2), __hmul2(E1bx2[1], e2b)),
                                     mtab[(m1 >> (p * 8)) & 3]);
                areg[p * 2] = h2u(w0);
                areg[p * 2 + 1] = h2u(w1);
            }
            uint32_t bq[8][2];
#pragma unroll
            for (int p = 0; p < 4; p++) {
                uint32_t addr = Bb2 + (ks * 16 + (g & 1) * 8 + (l & 7)) * 144
                              + (p * 2 + (g >> 1)) * 16;
                LDSM_X4T(bq[p * 2][0], bq[p * 2][1], bq[p * 2 + 1][0], bq[p * 2 + 1][1], addr);
            }
#pragma unroll
            for (int nt = 0; nt < 8; nt++)
                mma16816(c[nt], areg[0], areg[1], areg[2], areg[3], bq[nt][0], bq[nt][1]);
            mma16816(cden, areg[0], areg[1], areg[2], areg[3], ones_b, ones_b);
        }
    }

    float den0 = __shfl_sync(0xffffffffu, cden[0], l & ~3);
    float den1 = __shfl_sync(0xffffffffu, cden[2], l & ~3);
    float inv0 = 1.f / den0, inv1 = 1.f / den1;
#pragma unroll
    for (int nt = 0; nt < 8; nt++) {
        int col = nt * 8 + jb;
        float v;
        v = c[nt][0] * inv0; v = (v > 0.f) ? v : expm1f(v);
        atomicAdd(&g_Z[(size_t)(i0 + rq) * 64 + col], 0.125f * v);
        v = c[nt][1] * inv0; v = (v > 0.f) ? v : expm1f(v);
        atomicAdd(&g_Z[(size_t)(i0 + rq) * 64 + col + 1], 0.125f * v);
        v = c[nt][2] * inv1; v = (v > 0.f) ? v : expm1f(v);
        atomicAdd(&g_Z[(size_t)(i0 + rq + 8) * 64 + col], 0.125f * v);
        v = c[nt][3] * inv1; v = (v > 0.f) ? v : expm1f(v);
        atomicAdd(&g_Z[(size_t)(i0 + rq + 8) * 64 + col + 1], 0.125f * v);
    }
}

// ---------------- K4: h2 = z @ W_out; float4 cols per thread; pad col56=1 ----------------
__global__ __launch_bounds__(256) void k4_h2(const float* __restrict__ W_out,
                                             const float* __restrict__ a_out) {
    __shared__ float Wo[64 * 56];
    __shared__ float ao[112];
    __shared__ float zs[16 * 64];
    __shared__ float h2s[16 * 56];
    int t = threadIdx.x, w = t >> 5, l = t & 31;
    int i0 = blockIdx.x * 16;
    for (int idx = t; idx < 64 * 56; idx += 256) Wo[idx] = W_out[idx];
    if (t < 112) ao[t] = a_out[t];
    *(float4*)&zs[t * 4] = *(const float4*)&g_Z[(size_t)(i0 + (t >> 4)) * 64 + (t & 15) * 4];
    __syncthreads();
    if (t < 224) {
        int i = t / 14, c4 = (t % 14) * 4;
        float ax = 0.f, ay = 0.f, az = 0.f, aw2 = 0.f;
#pragma unroll
        for (int k = 0; k < 64; k++) {
            float a = zs[i * 64 + k];
            float4 w4 = *(const float4*)&Wo[k * 56 + c4];
            ax = fmaf(a, w4.x, ax); ay = fmaf(a, w4.y, ay);
            az = fmaf(a, w4.z, az); aw2 = fmaf(a, w4.w, aw2);
        }
        h2s[i * 56 + c4] = ax; h2s[i * 56 + c4 + 1] = ay;
        h2s[i * 56 + c4 + 2] = az; h2s[i * 56 + c4 + 3] = aw2;
        *(uint32_t*)(g_H2f16 + (size_t)(i0 + i) * 64 + c4) = packh2(ax, ay);
        *(uint32_t*)(g_H2f16 + (size_t)(i0 + i) * 64 + c4 + 2) = packh2(az, aw2);
    }
    if (t < 16) g_H2f16[(size_t)(i0 + t) * 64 + 56] = __float2half(1.f);
    if (t >= 32 && t < 144) {
        int u = t - 32;
        g_H2f16[(size_t)(i0 + u / 7) * 64 + 57 + (u % 7)] = __float2half(0.f);
    }
    __syncthreads();
#pragma unroll
    for (int rr = 0; rr < 2; rr++) {
        int row = w * 2 + rr;
        float v1 = h2s[row * 56 + l];
        float v2 = (l < 24) ? h2s[row * 56 + 32 + l] : 0.f;
        float s1 = v1 * ao[l] + ((l < 24) ? v2 * ao[32 + l] : 0.f);
        float s2 = v1 * ao[56 + l] + ((l < 24) ? v2 * ao[88 + l] : 0.f);
#pragma unroll
        for (int o = 16; o > 0; o >>= 1) {
            s1 += __shfl_xor_sync(0xffffffffu, s1, o);
            s2 += __shfl_xor_sync(0xffffffffu, s2, o);
        }
        if (l == 0) {
            int i = i0 + row;
            g_E1oh[i]  = __float2half(expf(s1));
            g_E1boh[i] = __float2half(expf(0.2f * s1));
            g_E2oh[i]  = __float2half(expf(s2));
            g_E2boh[i] = __float2half(expf(0.2f * s2));
        }
    }
}

// ---------------- K5: layer-2 aggregation; den = col 56 ----------------
__global__ __launch_bounds__(256, 2) void k5_mma() {
    __shared__ __align__(16) char Bsm[3][9216];
    __shared__ __align__(16) char scSm[3][256];
    __shared__ __half2 mtab[4];
    uint32_t Bb = s2u(Bsm), scb = s2u(scSm);
    int t = threadIdx.x, w = t >> 5, l = t & 31;
    int i0 = blockIdx.x * 128, jbeg = blockIdx.y * 512;
    int rq = w * 16 + (l >> 2);
    int jb = 2 * (l & 3);
    int g = l >> 3;
    if (t < 4) mtab[t] = __floats2half2_rn((t & 1) ? 1.f : 0.f, (t >> 1) ? 1.f : 0.f);

    __half2 E1x2[2], E1bx2[2];
#pragma unroll
    for (int r = 0; r < 2; r++) {
        int gidx = i0 + rq + r * 8;
        E1x2[r] = __half2half2(g_E1oh[gidx]);
        E1bx2[r] = __half2half2(g_E1boh[gidx]);
    }
    float c[8][4] = {};

    auto issue = [&](int buf, int jc) {
#pragma unroll
        for (int p = 0; p < 2; p++) {
            int idx = p * 256 + t;
            int j = idx >> 3, q = idx & 7;
            cpa16(Bb + buf * 9216 + j * 144 + q * 16,
                  g_H2f16 + (size_t)(jc + j) * 64 + q * 8);
        }
        if (t < 64) {
            int type = t >> 5, jj = t & 31;
            const __half* srcp = (type ? g_E2boh : g_E2oh) + jc + jj * 2;
            cpa4(scb + buf * 256 + type * 128 + jj * 4, srcp);
        }
    };
    issue(0, jbeg);      CP_COMMIT();
    issue(1, jbeg + 64); CP_COMMIT();

    for (int s = 0; s < 8; s++) {
        int jc = jbeg + s * 64, buf = s - (s / 3) * 3;
        CP_WAIT1();
        __syncthreads();
        if (s < 6) issue((s + 2) - ((s + 2) / 3) * 3, jc + 128);
        CP_COMMIT();

        const __half* scE2 = (const __half*)(scSm[buf]);
        uint32_t aw0[2], aw1[2];
        {
            uint2 a0 = *(const uint2*)&g_adjbits[(size_t)(i0 + rq) * 128 + (jc >> 5)];
            uint2 a1 = *(const uint2*)&g_adjbits[(size_t)(i0 + rq + 8) * 128 + (jc >> 5)];
            aw0[0] = a0.x; aw0[1] = a0.y;
            aw1[0] = a1.x; aw1[1] = a1.y;
        }
        uint32_t Bb2 = Bb + buf * 9216;
#pragma unroll
        for (int ks = 0; ks < 4; ks++) {
            uint32_t sh = (ks & 1) * 16 + jb;
            uint32_t m0 = aw0[ks >> 1] >> sh;
            uint32_t m1 = aw1[ks >> 1] >> sh;
            uint32_t areg[4];
#pragma unroll
            for (int p = 0; p < 2; p++) {
                int j0 = ks * 16 + jb + p * 8;
                __half2 e2  = *(const __half2*)(scE2 + j0);
                __half2 e2b = *(const __half2*)(scE2 + 64 + j0);
                __half2 w0 = __hmul2(__hmax2(__hmul2(E1x2[0], e2), __hmul2(E1bx2[0], e2b)),
                                     mtab[(m0 >> (p * 8)) & 3]);
                __half2 w1 = __hmul2(__hmax2(__hmul2(E1x2[1], e2), __hmul2(E1bx2[1], e2b)),
                                     mtab[(m1 >> (p * 8)) & 3]);
                areg[p * 2] = h2u(w0);
                areg[p * 2 + 1] = h2u(w1);
            }
            uint32_t bq[8][2];
#pragma unroll
            for (int p = 0; p < 4; p++) {
                uint32_t addr = Bb2 + (ks * 16 + (g & 1) * 8 + (l & 7)) * 144
                              + (p * 2 + (g >> 1)) * 16;
                LDSM_X4T(bq[p * 2][0], bq[p * 2][1], bq[p * 2 + 1][0], bq[p * 2 + 1][1], addr);
            }
#pragma unroll
            for (int nt = 0; nt < 8; nt++)
                mma16816(c[nt], areg[0], areg[1], areg[2], areg[3], bq[nt][0], bq[nt][1]);
        }
    }

    // den = column 56 (ones col) = c[7] cols 56/… from quad leader
    float den0 = __shfl_sync(0xffffffffu, c[7][0], l & ~3);
    float den1 = __shfl_sync(0xffffffffu, c[7][2], l & ~3);
    if ((l & 3) == 0) {
        atomicAdd(&g_den2[i0 + rq], den0);
        atomicAdd(&g_den2[i0 + rq + 8], den1);
    }
#pragma unroll
    for (int nt = 0; nt < 7; nt++) {
        int col = nt * 8 + jb;
        atomicAdd(&g_num2[(size_t)(i0 + rq) * NOUT + col], c[nt][0]);
        atomicAdd(&g_num2[(size_t)(i0 + rq) * NOUT + col + 1], c[nt][1]);
        atomicAdd(&g_num2[(size_t)(i0 + rq + 8) * NOUT + col], c[nt][2]);
        atomicAdd(&g_num2[(size_t)(i0 + rq + 8) * NOUT + col + 1], c[nt][3]);
    }
}

// ---------------- K6: out = softmax(elu(num2/den2)) ----------------
__global__ __launch_bounds__(256) void k6_final(float* __restrict__ out) {
    int wid = (blockIdx.x * 256 + threadIdx.x) >> 5;
    int lane = threadIdx.x & 31;
    if (wid >= N) return;
    float invd = 1.0f / g_den2[wid];
    float v1 = g_num2[(size_t)wid * NOUT + lane] * invd;
    v1 = (v1 > 0.f) ? v1 : expm1f(v1);
    float v2 = -1e30f;
    if (lane < 24) {
        v2 = g_num2[(size_t)wid * NOUT + 32 + lane] * invd;
        v2 = (v2 > 0.f) ? v2 : expm1f(v2);
    }
    float m = fmaxf(v1, v2);
#pragma unroll
    for (int o = 16; o > 0; o >>= 1) m = fmaxf(m, __shfl_xor_sync(0xffffffffu, m, o));
    float e1 = expf(v1 - m);
    float e2 = (lane < 24) ? expf(v2 - m) : 0.f;
    float s = e1 + e2;
#pragma unroll
    for (int o = 16; o > 0; o >>= 1) s += __shfl_xor_sync(0xffffffffu, s, o);
    float invs = 1.0f / s;
    out[(size_t)wid * NOUT + lane] = e1 * invs;
    if (lane < 24) out[(size_t)wid * NOUT + 32 + lane] = e2 * invs;
}

// ---------------- launch ----------------
extern "C" void kernel_launch(void* const* d_in, const int* in_sizes, int n_in,
                              void* d_out, int out_size) {
    (void)in_sizes; (void)n_in; (void)out_size;
    const float* x     = (const float*)d_in[0];
    const int*   adj   = (const int*)d_in[1];
    const float* Ws    = (const float*)d_in[2];
    const float* As_   = (const float*)d_in[3];
    const float* W_out = (const float*)d_in[4];
    const float* a_out = (const float*)d_in[5];
    float* out = (float*)d_out;

    cudaFuncSetAttribute(k3_mma, cudaFuncAttributeMaxDynamicSharedMemorySize, K3_SMEM);

    kA_init<<<2048, 256>>>(x, Ws, adj);
    k1_mma<<<dim3(64, 8), 128>>>(As_);
    k3_mma<<<dim3(64, 4), 256, K3_SMEM>>>();
    k4_h2<<<256, 256>>>(W_out, a_out);
    k5_mma<<<dim3(32, 8), 256>>>();
    k6_final<<<512, 256>>>(out);
}